// round 10
// baseline (speedup 1.0000x reference)
#include <cuda_runtime.h>
#include <cuda_fp16.h>
#include <math.h>
#include <stdint.h>

#define BB   4
#define CC   32
#define NN   2048
#define PP   12
#define OUTC 32
#define TM   64
#define KT   64
#define THREADS 256
#define EPSV 1e-5f
#define NEG_SLOPE 0.01f

// ---- smem layout ----
// stage: A[64][72 fp16] = 9216 B ; F[256][72 fp16] = 36864 B
#define A_BYTES   9216
#define SB_BYTES  46080
#define NBUF      2
// epilogue: ACC f32 [64][264] = 67584 B, then feats fp16 [64][116 u32] after it
#define ACCS      264
#define FEAT_OFF  16896              // u32 offset (= 67584 B)
#define FBS       116
#define THB_OFF   0                  // ThetaB staged into dead ACC region after phase A
#define SMEM_BYTES 97280             // max(ring 92160, ACC+feats 97280)

__device__ __half g_ahf[(size_t)NN * NN];               // fp16 A
__device__ __half g_fhf[(size_t)BB * PP * 256 * NN];    // fp16 features [bp][256][j]
__device__ float g_xp[(size_t)BB * PP * NN * CC];
__device__ float g_deg[NN];
__device__ float g_delta;

// ---------------------------------------------------------------------------
__device__ __forceinline__ uint32_t smem_u32(const void* p) {
    uint32_t a;
    asm("{ .reg .u64 t; cvta.to.shared.u64 t, %1; cvt.u32.u64 %0, t; }" : "=r"(a) : "l"(p));
    return a;
}
#define CP16(dst, src) \
    asm volatile("cp.async.cg.shared.global [%0], [%1], 16;\n" \
                 :: "r"(dst), "l"(src) : "memory")
#define CP_COMMIT() asm volatile("cp.async.commit_group;\n" ::: "memory")
#define CP_WAIT1()  asm volatile("cp.async.wait_group 1;\n" ::: "memory")

__device__ __forceinline__ void ldsm_x4(uint32_t r[4], uint32_t addr) {
    asm volatile("ldmatrix.sync.aligned.m8n8.x4.shared.b16 {%0,%1,%2,%3}, [%4];"
        : "=r"(r[0]), "=r"(r[1]), "=r"(r[2]), "=r"(r[3]) : "r"(addr));
}
__device__ __forceinline__ void mma_f16(float c[4], const uint32_t a[4],
                                        const uint32_t b0, const uint32_t b1) {
    asm volatile(
        "mma.sync.aligned.m16n8k16.row.col.f32.f16.f16.f32 "
        "{%0,%1,%2,%3}, {%4,%5,%6,%7}, {%8,%9}, {%0,%1,%2,%3};"
        : "+f"(c[0]), "+f"(c[1]), "+f"(c[2]), "+f"(c[3])
        : "r"(a[0]), "r"(a[1]), "r"(a[2]), "r"(a[3]), "r"(b0), "r"(b1));
}
__device__ __forceinline__ uint32_t pack_h2(float lo, float hi) {
    __half2 h = __floats2half2_rn(lo, hi);
    return *reinterpret_cast<uint32_t*>(&h);
}

// ---------------------------------------------------------------------------
__global__ void deg_kernel(const float* __restrict__ A) {
    int row  = blockIdx.x * (blockDim.x >> 5) + (threadIdx.x >> 5);
    int lane = threadIdx.x & 31;
    const float* r = A + (size_t)row * NN;
    float s = 0.f;
    for (int j = lane; j < NN; j += 32) s += r[j];
    #pragma unroll
    for (int o = 16; o; o >>= 1) s += __shfl_xor_sync(0xffffffffu, s, o);
    if (lane == 0) g_deg[row] = s;
}

__global__ void delta_kernel() {
    __shared__ float red[32];
    int tid = threadIdx.x;
    float s = 0.f;
    for (int i = tid; i < NN; i += blockDim.x) s += logf(g_deg[i] + 1.f);
    #pragma unroll
    for (int o = 16; o; o >>= 1) s += __shfl_xor_sync(0xffffffffu, s, o);
    if ((tid & 31) == 0) red[tid >> 5] = s;
    __syncthreads();
    if (tid < 32) {
        float v = (tid < (int)(blockDim.x >> 5)) ? red[tid] : 0.f;
        #pragma unroll
        for (int o = 16; o; o >>= 1) v += __shfl_xor_sync(0xffffffffu, v, o);
        if (tid == 0) g_delta = v / (float)NN;
    }
}

__global__ void transpose_kernel(const float* __restrict__ X) {
    int idx = blockIdx.x * blockDim.x + threadIdx.x;
    if (idx >= BB * PP * NN * CC) return;
    int ch = idx & (CC - 1);
    int j  = (idx >> 5) & (NN - 1);
    int bp = idx >> 16;
    int b = bp / PP, p = bp % PP;
    g_xp[idx] = X[(((size_t)b * CC + ch) * NN + j) * PP + p];
}

__global__ void ahf_kernel(const float* __restrict__ A) {
    int idx = blockIdx.x * blockDim.x + threadIdx.x;
    if (idx >= NN * NN / 2) return;
    float2 v = reinterpret_cast<const float2*>(A)[idx];
    reinterpret_cast<uint32_t*>(g_ahf)[idx] = pack_h2(v.x, v.y);
}

__global__ void fhf_kernel() {
    __shared__ float sx[64][33];
    int bp = blockIdx.y, j0 = blockIdx.x * 64;
    int t = threadIdx.x;   // 256
    #pragma unroll
    for (int k = 0; k < 8; k++) {
        int idx = t + k * 256;
        sx[idx >> 5][idx & 31] = g_xp[((size_t)bp * NN + j0 + (idx >> 5)) * CC + (idx & 31)];
    }
    __syncthreads();
    int jp = t & 31;
    int chb = t >> 5;
    uint32_t* dst = reinterpret_cast<uint32_t*>(g_fhf);
    #pragma unroll
    for (int it = 0; it < 4; it++) {
        int ch = chb * 4 + it;
        float x0 = sx[2 * jp][ch],  x1 = sx[2 * jp + 1][ch];
        float a2 = x0 * x0, b2 = x1 * x1;
        float e0 = expf(x0), e1 = expf(x1);
        float n0 = expf(-x0), n1 = expf(-x1);
        size_t base = (((size_t)bp * 256 + ch) * NN + j0) / 2 + jp;
        const size_t G = (size_t)32 * NN / 2;
        dst[base + 0 * G] = pack_h2(x0, x1);
        dst[base + 1 * G] = pack_h2(a2, b2);
        dst[base + 2 * G] = pack_h2(a2 * x0, b2 * x1);
        dst[base + 3 * G] = pack_h2(a2 * a2, b2 * b2);
        dst[base + 4 * G] = pack_h2(x0 * e0, x1 * e1);
        dst[base + 5 * G] = pack_h2(e0, e1);
        dst[base + 6 * G] = pack_h2(x0 * n0, x1 * n1);
        dst[base + 7 * G] = pack_h2(n0, n1);
    }
}

// ---------------------------------------------------------------------------
__global__ __launch_bounds__(THREADS, 2)
void pna_kernel(const float* __restrict__ Theta, const float* __restrict__ Bias,
                float* __restrict__ out) {
    extern __shared__ uint32_t smu[];
    const uint32_t sbase = smem_u32(smu);

    const int tid = threadIdx.x, lane = tid & 31, wid = tid >> 5;
    const int lq = lane >> 2, lr = lane & 3;
    const int wm = wid >> 2, wn = wid & 3;      // 2x4 warps, warp tile 32x64
    const int bp = blockIdx.y, i0 = blockIdx.x * TM;
    const int b = bp / PP, p = bp % PP;

    // ---- cp.async staging addresses (fp16, 144B row stride) ----
    const __half* a_src = g_ahf + (size_t)(i0 + (tid >> 2)) * NN + (tid & 3) * 16;
    const __half* f_src = g_fhf + ((size_t)bp * 256 + tid) * NN;
    const uint32_t a_dst = sbase + (tid >> 2) * 144 + (tid & 3) * 32;
    const uint32_t f_dst = sbase + A_BYTES + tid * 144;

    #define ISSUE(s) do {                                                     \
        uint32_t _sb = (uint32_t)(((s) & 1) * SB_BYTES);                      \
        const __half* _as = a_src + (size_t)(s) * KT;                         \
        const __half* _fs = f_src + (size_t)(s) * KT;                         \
        CP16(a_dst + _sb,      _as);                                          \
        CP16(a_dst + _sb + 16, _as + 8);                                      \
        _Pragma("unroll")                                                     \
        for (int _j = 0; _j < 8; _j++)                                        \
            CP16(f_dst + _sb + _j * 16, _fs + _j * 8);                        \
        CP_COMMIT();                                                          \
    } while (0)

    // ldmatrix per-lane base addresses
    const uint32_t a_lm = sbase +
        (wm * 32 + (lane & 7) + ((lane >> 3) & 1) * 8) * 144 + ((lane >> 4) & 1) * 16;
    const uint32_t b_lm = sbase + A_BYTES +
        (wn * 64 + (lane & 7) + ((lane >> 4) & 1) * 8) * 144 + ((lane >> 3) & 1) * 16;

    float acc[2][8][4];
    #pragma unroll
    for (int mt = 0; mt < 2; mt++)
        #pragma unroll
        for (int nt = 0; nt < 8; nt++)
            #pragma unroll
            for (int j = 0; j < 4; j++) acc[mt][nt][j] = 0.f;

    ISSUE(0);
    ISSUE(1);

    const int NST = NN / KT;   // 32
    for (int s = 0; s < NST; s++) {
        CP_WAIT1();
        __syncthreads();

        const uint32_t stg = (uint32_t)((s & 1) * SB_BYTES);
        #pragma unroll
        for (int kb = 0; kb < 4; kb++) {
            uint32_t af[2][4], bf[4][4];
            #pragma unroll
            for (int mt = 0; mt < 2; mt++)
                ldsm_x4(af[mt], a_lm + stg + mt * 2304 + kb * 32);
            #pragma unroll
            for (int ntp = 0; ntp < 4; ntp++)
                ldsm_x4(bf[ntp], b_lm + stg + ntp * 2304 + kb * 32);
            #pragma unroll
            for (int mt = 0; mt < 2; mt++)
                #pragma unroll
                for (int nt = 0; nt < 8; nt++)
                    mma_f16(acc[mt][nt], af[mt], bf[nt >> 1][(nt & 1) * 2],
                            bf[nt >> 1][(nt & 1) * 2 + 1]);
        }
        __syncthreads();
        if (s + 2 < NST) ISSUE(s + 2); else CP_COMMIT();   // keep group invariant
    }
    #undef ISSUE

    // ---- spill accumulators to ACC[64][264] f32 ----
    float* ACCf = reinterpret_cast<float*>(smu);
    #pragma unroll
    for (int mt = 0; mt < 2; mt++) {
        int r = wm * 32 + mt * 16 + lq;
        #pragma unroll
        for (int nt = 0; nt < 8; nt++) {
            int c = wn * 64 + nt * 8 + lr * 2;
            float* a = acc[mt][nt];
            ACCf[r * ACCS + c]           = a[0];
            ACCf[r * ACCS + c + 1]       = a[1];
            ACCf[(r + 8) * ACCS + c]     = a[2];
            ACCf[(r + 8) * ACCS + c + 1] = a[3];
        }
    }
    __syncthreads();

    // ---- phase A: aggregators -> feats fp16 [64][2*FBS] ----
    __half* Fbh = reinterpret_cast<__half*>(smu + FEAT_OFF);
    const float* xp = g_xp + (size_t)bp * NN * CC;
    for (int e = tid; e < TM * 32; e += THREADS) {
        int il = e >> 5, ch = e & 31;
        const float* row = &ACCf[il * ACCS];
        float S1  = row[ch],       S2  = row[32 + ch];
        float S3  = row[64 + ch],  S4  = row[96 + ch];
        float SXP = row[128 + ch], SEP = row[160 + ch];
        float SXN = row[192 + ch], SEN = row[224 + ch];

        int i = i0 + il;
        float x    = xp[(size_t)i * CC + ch];
        float dg   = g_deg[i];
        float dinv = 1.f / fmaxf(dg, EPSV);
        float m1 = S1 * dinv, m2 = S2 * dinv, m3 = S3 * dinv, m4 = S4 * dinv;
        float smax = SXP / (SEP + EPSV);
        float smin = SXN / (SEN + EPSV);
        float var  = fmaxf(m2 - m1 * m1, 0.f);
        float stdv = sqrtf(var + EPSV);
        float x2 = x * x, x3 = x2 * x, x4 = x2 * x2;
        float dist = x2 - 2.f * x * m1 + m2;
        float ed2  = x4 - 4.f * x3 * m1 + 6.f * x2 * m2 - 4.f * x * m3 + m4;
        float dstd = sqrtf(fmaxf(ed2 - dist * dist, 0.f) + EPSV);

        __half* fr = Fbh + (size_t)il * (2 * FBS);
        fr[0 * 32 + ch] = __float2half(smin);
        fr[1 * 32 + ch] = __float2half(smax);
        fr[2 * 32 + ch] = __float2half(m1);
        fr[3 * 32 + ch] = __float2half(stdv);
        fr[4 * 32 + ch] = __float2half(var);
        fr[5 * 32 + ch] = __float2half(dist);
        fr[6 * 32 + ch] = __float2half(dstd);
    }
    __syncthreads();

    // ---- stage ThetaB [96 n][112 k-pairs] fp16 into dead ACC region ----
    for (int idx = tid; idx < 96 * 112; idx += THREADS) {
        int p2 = idx / 96, n = idx % 96;
        int q = n >> 5, o = n & 31;
        float f0 = Theta[(size_t)(224 * q + 2 * p2) * OUTC + o];
        float f1 = Theta[(size_t)(224 * q + 2 * p2 + 1) * OUTC + o];
        smu[THB_OFF + n * FBS + p2] = pack_h2(f0, f1);
    }
    __syncthreads();

    // ---- GEMM2 (fp16): D[64][96] = feats[64x224] @ ThetaB^T ----
    {
        const uint32_t* Fb = smu + FEAT_OFF;
        const uint32_t* Tb = smu + THB_OFF;
        const int wm2 = wid >> 1, wn2 = wid & 1;   // 4 x 2 warps: 16 rows x 48 cols
        float a2[6][4];
        #pragma unroll
        for (int nt = 0; nt < 6; nt++)
            #pragma unroll
            for (int j = 0; j < 4; j++) a2[nt][j] = 0.f;

        #pragma unroll 2
        for (int kb = 0; kb < 14; kb++) {
            uint32_t af[4], bfv[6][2];
            int r = (wm2 * 16 + lq) * FBS + kb * 8 + lr;
            af[0] = Fb[r];
            af[1] = Fb[r + 8 * FBS];
            af[2] = Fb[r + 4];
            af[3] = Fb[r + 8 * FBS + 4];
            #pragma unroll
            for (int nt = 0; nt < 6; nt++) {
                int c = (wn2 * 48 + nt * 8 + lq) * FBS + kb * 8 + lr;
                bfv[nt][0] = Tb[c];
                bfv[nt][1] = Tb[c + 4];
            }
            #pragma unroll
            for (int nt = 0; nt < 6; nt++)
                mma_f16(a2[nt], af, bfv[nt][0], bfv[nt][1]);
        }
        __syncthreads();
        // spill D[64][100] into ThetaB region (dead now)
        float* D = reinterpret_cast<float*>(smu);
        int r = wm2 * 16 + lq;
        #pragma unroll
        for (int nt = 0; nt < 6; nt++) {
            int c = wn2 * 48 + nt * 8 + 2 * lr;
            D[r * 100 + c]           = a2[nt][0];
            D[r * 100 + c + 1]       = a2[nt][1];
            D[(r + 8) * 100 + c]     = a2[nt][2];
            D[(r + 8) * 100 + c + 1] = a2[nt][3];
        }
        __syncthreads();

        // ---- combine: out = D0 + s*D1 + inv*D2 + bias, leaky relu ----
        int i = tid >> 2;
        int ob = (tid & 3) * 8;
        float dg = g_deg[i0 + i];
        float sv = logf(dg + 1.f) / g_delta;
        float iv = 1.f / fmaxf(sv, EPSV);
        #pragma unroll
        for (int k = 0; k < 8; k++) {
            int o = ob + k;
            float v = D[i * 100 + o] + sv * D[i * 100 + 32 + o] +
                      iv * D[i * 100 + 64 + o] + Bias[o];
            v = v > 0.f ? v : NEG_SLOPE * v;
            out[(((size_t)b * OUTC + o) * NN + (i0 + i)) * PP + p] = v;
        }
    }
}

// ---------------------------------------------------------------------------
extern "C" void kernel_launch(void* const* d_in, const int* in_sizes, int n_in,
                              void* d_out, int out_size) {
    const float* X     = (const float*)d_in[0];
    const float* A     = (const float*)d_in[1];
    const float* Theta = (const float*)d_in[2];
    const float* Bias  = (const float*)d_in[3];
    float* out = (float*)d_out;

    cudaFuncSetAttribute(pna_kernel, cudaFuncAttributeMaxDynamicSharedMemorySize,
                         SMEM_BYTES);

    deg_kernel<<<NN / 8, 256>>>(A);
    delta_kernel<<<1, 1024>>>();
    transpose_kernel<<<(BB * PP * NN * CC + 255) / 256, 256>>>(X);
    ahf_kernel<<<(NN * NN / 2 + 1023) / 1024, 1024>>>(A);
    fhf_kernel<<<dim3(NN / 64, BB * PP), 256>>>();

    dim3 grid(NN / TM, BB * PP);
    pna_kernel<<<grid, THREADS, SMEM_BYTES>>>(Theta, Bias, out);
}

// round 11
// speedup vs baseline: 1.2471x; 1.2471x over previous
#include <cuda_runtime.h>
#include <cuda_fp16.h>
#include <math.h>
#include <stdint.h>

#define BB   4
#define CC   32
#define NN   2048
#define PP   12
#define OUTC 32
#define TM   128
#define KT   64
#define THREADS 512
#define EPSV 1e-5f
#define NEG_SLOPE 0.01f

// ---- smem layout ----
// stage: A[128][72 fp16] = 18432 B ; F[256][72 fp16] = 36864 B
#define A_BYTES   18432
#define SB_BYTES  55296
#define NBUF      4
#define SMEM_BYTES (NBUF * SB_BYTES)      // 221184
// epilogue regions (u32 offsets, reuse ring after mainloop)
#define ACCS     264
#define FEAT_OFF 16896
#define FBS      116
#define THB_OFF  31744

__device__ __half g_ahf[(size_t)NN * NN];               // fp16 A
__device__ __half g_fhf[(size_t)BB * PP * 256 * NN];    // fp16 features [bp][256][j]
__device__ float g_xp[(size_t)BB * PP * NN * CC];
__device__ float g_deg[NN];
__device__ float g_delta;

// ---------------------------------------------------------------------------
__device__ __forceinline__ uint32_t smem_u32(const void* p) {
    uint32_t a;
    asm("{ .reg .u64 t; cvta.to.shared.u64 t, %1; cvt.u32.u64 %0, t; }" : "=r"(a) : "l"(p));
    return a;
}
#define CP16(dst, src) \
    asm volatile("cp.async.cg.shared.global [%0], [%1], 16;\n" \
                 :: "r"(dst), "l"(src) : "memory")
#define CP_COMMIT() asm volatile("cp.async.commit_group;\n" ::: "memory")
#define CP_WAIT2()  asm volatile("cp.async.wait_group 2;\n" ::: "memory")

__device__ __forceinline__ void ldsm_x4(uint32_t r[4], uint32_t addr) {
    asm volatile("ldmatrix.sync.aligned.m8n8.x4.shared.b16 {%0,%1,%2,%3}, [%4];"
        : "=r"(r[0]), "=r"(r[1]), "=r"(r[2]), "=r"(r[3]) : "r"(addr));
}
__device__ __forceinline__ void mma_f16(float c[4], const uint32_t a[4],
                                        const uint32_t b0, const uint32_t b1) {
    asm volatile(
        "mma.sync.aligned.m16n8k16.row.col.f32.f16.f16.f32 "
        "{%0,%1,%2,%3}, {%4,%5,%6,%7}, {%8,%9}, {%0,%1,%2,%3};"
        : "+f"(c[0]), "+f"(c[1]), "+f"(c[2]), "+f"(c[3])
        : "r"(a[0]), "r"(a[1]), "r"(a[2]), "r"(a[3]), "r"(b0), "r"(b1));
}
__device__ __forceinline__ uint32_t pack_h2(float lo, float hi) {
    __half2 h = __floats2half2_rn(lo, hi);
    return *reinterpret_cast<uint32_t*>(&h);
}

// ---------------------------------------------------------------------------
__global__ void deg_kernel(const float* __restrict__ A) {
    int row  = blockIdx.x * (blockDim.x >> 5) + (threadIdx.x >> 5);
    int lane = threadIdx.x & 31;
    const float* r = A + (size_t)row * NN;
    float s = 0.f;
    for (int j = lane; j < NN; j += 32) s += r[j];
    #pragma unroll
    for (int o = 16; o; o >>= 1) s += __shfl_xor_sync(0xffffffffu, s, o);
    if (lane == 0) g_deg[row] = s;
}

__global__ void delta_kernel() {
    __shared__ float red[32];
    int tid = threadIdx.x;
    float s = 0.f;
    for (int i = tid; i < NN; i += blockDim.x) s += logf(g_deg[i] + 1.f);
    #pragma unroll
    for (int o = 16; o; o >>= 1) s += __shfl_xor_sync(0xffffffffu, s, o);
    if ((tid & 31) == 0) red[tid >> 5] = s;
    __syncthreads();
    if (tid < 32) {
        float v = (tid < (int)(blockDim.x >> 5)) ? red[tid] : 0.f;
        #pragma unroll
        for (int o = 16; o; o >>= 1) v += __shfl_xor_sync(0xffffffffu, v, o);
        if (tid == 0) g_delta = v / (float)NN;
    }
}

__global__ void ahf_kernel(const float* __restrict__ A) {
    int idx = blockIdx.x * blockDim.x + threadIdx.x;
    if (idx >= NN * NN / 2) return;
    float2 v = reinterpret_cast<const float2*>(A)[idx];
    reinterpret_cast<uint32_t*>(g_ahf)[idx] = pack_h2(v.x, v.y);
}

// fused: transpose X -> g_xp AND build fp16 feature planes g_fhf
__global__ void xf_kernel(const float* __restrict__ X) {
    int bp = blockIdx.y, j0 = blockIdx.x * 64;
    int b = bp / PP, p = bp % PP;
    int t = threadIdx.x;   // 256
    int jp = t & 31;       // j-pair within 64-block
    int chb = t >> 5;      // 0..7
    uint32_t* dst = reinterpret_cast<uint32_t*>(g_fhf);
    float* xpd = g_xp + (size_t)bp * NN * CC;
    #pragma unroll
    for (int it = 0; it < 4; it++) {
        int ch = chb * 4 + it;
        int j = j0 + 2 * jp;
        float x0 = X[(((size_t)b * CC + ch) * NN + j) * PP + p];
        float x1 = X[(((size_t)b * CC + ch) * NN + j + 1) * PP + p];
        xpd[(size_t)j * CC + ch]       = x0;
        xpd[(size_t)(j + 1) * CC + ch] = x1;
        float a2 = x0 * x0, b2 = x1 * x1;
        float e0 = expf(x0), e1 = expf(x1);
        float n0 = expf(-x0), n1 = expf(-x1);
        size_t base = (((size_t)bp * 256 + ch) * NN + j0) / 2 + jp;
        const size_t G = (size_t)32 * NN / 2;
        dst[base + 0 * G] = pack_h2(x0, x1);
        dst[base + 1 * G] = pack_h2(a2, b2);
        dst[base + 2 * G] = pack_h2(a2 * x0, b2 * x1);
        dst[base + 3 * G] = pack_h2(a2 * a2, b2 * b2);
        dst[base + 4 * G] = pack_h2(x0 * e0, x1 * e1);
        dst[base + 5 * G] = pack_h2(e0, e1);
        dst[base + 6 * G] = pack_h2(x0 * n0, x1 * n1);
        dst[base + 7 * G] = pack_h2(n0, n1);
    }
}

// ---------------------------------------------------------------------------
__global__ __launch_bounds__(THREADS, 1)
void pna_kernel(const float* __restrict__ Theta, const float* __restrict__ Bias,
                float* __restrict__ out) {
    extern __shared__ uint32_t smu[];
    const uint32_t sbase = smem_u32(smu);

    const int tid = threadIdx.x, lane = tid & 31, wid = tid >> 5;
    const int lq = lane >> 2, lr = lane & 3;
    const int wm = wid >> 2, wn = wid & 3;      // 4x4 warps, warp tile 32x64
    const int bp = blockIdx.y, i0 = blockIdx.x * TM;
    const int b = bp / PP, p = bp % PP;

    // ---- cp.async staging addresses (fp16, 144B row stride) ----
    const __half* a_src = g_ahf + (size_t)(i0 + (tid >> 2)) * NN + (tid & 3) * 16;
    const __half* f_src = g_fhf + ((size_t)bp * 256 + (tid >> 1)) * NN + (tid & 1) * 32;
    const uint32_t a_dst = sbase + (tid >> 2) * 144 + (tid & 3) * 32;
    const uint32_t f_dst = sbase + A_BYTES + (tid >> 1) * 144 + (tid & 1) * 64;

    #define ISSUE(s) do {                                                     \
        uint32_t _sb = (uint32_t)(((s) & 3) * SB_BYTES);                      \
        const __half* _as = a_src + (size_t)(s) * KT;                         \
        const __half* _fs = f_src + (size_t)(s) * KT;                         \
        CP16(a_dst + _sb,      _as);                                          \
        CP16(a_dst + _sb + 16, _as + 8);                                      \
        CP16(f_dst + _sb,      _fs);                                          \
        CP16(f_dst + _sb + 16, _fs + 8);                                      \
        CP16(f_dst + _sb + 32, _fs + 16);                                     \
        CP16(f_dst + _sb + 48, _fs + 24);                                     \
        CP_COMMIT();                                                          \
    } while (0)

    // ldmatrix per-lane base addresses
    const uint32_t a_lm = sbase +
        (wm * 32 + (lane & 7) + ((lane >> 3) & 1) * 8) * 144 + ((lane >> 4) & 1) * 16;
    const uint32_t b_lm = sbase + A_BYTES +
        (wn * 64 + (lane & 7) + ((lane >> 4) & 1) * 8) * 144 + ((lane >> 3) & 1) * 16;

    float acc[2][8][4];
    #pragma unroll
    for (int mt = 0; mt < 2; mt++)
        #pragma unroll
        for (int nt = 0; nt < 8; nt++)
            #pragma unroll
            for (int j = 0; j < 4; j++) acc[mt][nt][j] = 0.f;

    ISSUE(0);
    ISSUE(1);
    ISSUE(2);

    const int NST = NN / KT;   // 32
    for (int s = 0; s < NST; s++) {
        CP_WAIT2();
        __syncthreads();                 // single barrier per stage:
        if (s + 3 < NST) ISSUE(s + 3);   // buffer (s+3)&3 was released by the
        else CP_COMMIT();                // barrier (all warps past MMA(s-1))

        const uint32_t stg = (uint32_t)((s & 3) * SB_BYTES);
        #pragma unroll
        for (int kb = 0; kb < 4; kb++) {
            uint32_t af[2][4], bf[4][4];
            #pragma unroll
            for (int mt = 0; mt < 2; mt++)
                ldsm_x4(af[mt], a_lm + stg + mt * 2304 + kb * 32);
            #pragma unroll
            for (int ntp = 0; ntp < 4; ntp++)
                ldsm_x4(bf[ntp], b_lm + stg + ntp * 2304 + kb * 32);
            #pragma unroll
            for (int mt = 0; mt < 2; mt++)
                #pragma unroll
                for (int nt = 0; nt < 8; nt++)
                    mma_f16(acc[mt][nt], af[mt], bf[nt >> 1][(nt & 1) * 2],
                            bf[nt >> 1][(nt & 1) * 2 + 1]);
        }
    }
    #undef ISSUE
    __syncthreads();   // all MMAs done before epilogue reuses the ring

    // ---- stage ThetaB [96 n][112 k-pairs] fp16 ----
    for (int idx = tid; idx < 96 * 112; idx += THREADS) {
        int p2 = idx / 96, n = idx % 96;
        int q = n >> 5, o = n & 31;
        float f0 = Theta[(size_t)(224 * q + 2 * p2) * OUTC + o];
        float f1 = Theta[(size_t)(224 * q + 2 * p2 + 1) * OUTC + o];
        smu[THB_OFF + n * FBS + p2] = pack_h2(f0, f1);
    }

    // ---- epilogue phase A in two 64-row halves ----
    float* ACCf = reinterpret_cast<float*>(smu);
    __half* Fbh = reinterpret_cast<__half*>(smu + FEAT_OFF);
    const float* xp = g_xp + (size_t)bp * NN * CC;

    #pragma unroll
    for (int h = 0; h < 2; h++) {
        if ((wm >> 1) == h) {
            #pragma unroll
            for (int mt = 0; mt < 2; mt++) {
                int r = (wm & 1) * 32 + mt * 16 + lq;
                #pragma unroll
                for (int nt = 0; nt < 8; nt++) {
                    int c = wn * 64 + nt * 8 + lr * 2;
                    float* a = acc[mt][nt];
                    ACCf[r * ACCS + c]           = a[0];
                    ACCf[r * ACCS + c + 1]       = a[1];
                    ACCf[(r + 8) * ACCS + c]     = a[2];
                    ACCf[(r + 8) * ACCS + c + 1] = a[3];
                }
            }
        }
        __syncthreads();
        for (int e = tid; e < 64 * 32; e += THREADS) {
            int il = e >> 5, ch = e & 31;
            const float* row = &ACCf[il * ACCS];
            float S1  = row[ch],       S2  = row[32 + ch];
            float S3  = row[64 + ch],  S4  = row[96 + ch];
            float SXP = row[128 + ch], SEP = row[160 + ch];
            float SXN = row[192 + ch], SEN = row[224 + ch];

            int i = i0 + 64 * h + il;
            float x    = xp[(size_t)i * CC + ch];
            float dg   = g_deg[i];
            float dinv = 1.f / fmaxf(dg, EPSV);
            float m1 = S1 * dinv, m2 = S2 * dinv, m3 = S3 * dinv, m4 = S4 * dinv;
            float smax = SXP / (SEP + EPSV);
            float smin = SXN / (SEN + EPSV);
            float var  = fmaxf(m2 - m1 * m1, 0.f);
            float stdv = sqrtf(var + EPSV);
            float x2 = x * x, x3 = x2 * x, x4 = x2 * x2;
            float dist = x2 - 2.f * x * m1 + m2;
            float ed2  = x4 - 4.f * x3 * m1 + 6.f * x2 * m2 - 4.f * x * m3 + m4;
            float dstd = sqrtf(fmaxf(ed2 - dist * dist, 0.f) + EPSV);

            __half* fr = Fbh + (size_t)(64 * h + il) * (2 * FBS);
            fr[0 * 32 + ch] = __float2half(smin);
            fr[1 * 32 + ch] = __float2half(smax);
            fr[2 * 32 + ch] = __float2half(m1);
            fr[3 * 32 + ch] = __float2half(stdv);
            fr[4 * 32 + ch] = __float2half(var);
            fr[5 * 32 + ch] = __float2half(dist);
            fr[6 * 32 + ch] = __float2half(dstd);
        }
        __syncthreads();
    }

    // ---- GEMM2 (fp16): D[128][96] = feats[128x224] @ ThetaB^T ----
    {
        const uint32_t* Fb = smu + FEAT_OFF;
        const uint32_t* Tb = smu + THB_OFF;
        const int wm2 = wid >> 1, wn2 = wid & 1;
        float a2[6][4];
        #pragma unroll
        for (int nt = 0; nt < 6; nt++)
            #pragma unroll
            for (int j = 0; j < 4; j++) a2[nt][j] = 0.f;

        #pragma unroll 2
        for (int kb = 0; kb < 14; kb++) {
            uint32_t af[4], bfv[6][2];
            int r = (wm2 * 16 + lq) * FBS + kb * 8 + lr;
            af[0] = Fb[r];
            af[1] = Fb[r + 8 * FBS];
            af[2] = Fb[r + 4];
            af[3] = Fb[r + 8 * FBS + 4];
            #pragma unroll
            for (int nt = 0; nt < 6; nt++) {
                int c = (wn2 * 48 + nt * 8 + lq) * FBS + kb * 8 + lr;
                bfv[nt][0] = Tb[c];
                bfv[nt][1] = Tb[c + 4];
            }
            #pragma unroll
            for (int nt = 0; nt < 6; nt++)
                mma_f16(a2[nt], af, bfv[nt][0], bfv[nt][1]);
        }
        __syncthreads();
        float* D = reinterpret_cast<float*>(smu);
        int r = wm2 * 16 + lq;
        #pragma unroll
        for (int nt = 0; nt < 6; nt++) {
            int c = wn2 * 48 + nt * 8 + 2 * lr;
            D[r * 100 + c]           = a2[nt][0];
            D[r * 100 + c + 1]       = a2[nt][1];
            D[(r + 8) * 100 + c]     = a2[nt][2];
            D[(r + 8) * 100 + c + 1] = a2[nt][3];
        }
        __syncthreads();

        int i = tid >> 2;
        int ob = (tid & 3) * 8;
        float dg = g_deg[i0 + i];
        float sv = logf(dg + 1.f) / g_delta;
        float iv = 1.f / fmaxf(sv, EPSV);
        #pragma unroll
        for (int k = 0; k < 8; k++) {
            int o = ob + k;
            float v = D[i * 100 + o] + sv * D[i * 100 + 32 + o] +
                      iv * D[i * 100 + 64 + o] + Bias[o];
            v = v > 0.f ? v : NEG_SLOPE * v;
            out[(((size_t)b * OUTC + o) * NN + (i0 + i)) * PP + p] = v;
        }
    }
}

// ---------------------------------------------------------------------------
extern "C" void kernel_launch(void* const* d_in, const int* in_sizes, int n_in,
                              void* d_out, int out_size) {
    const float* X     = (const float*)d_in[0];
    const float* A     = (const float*)d_in[1];
    const float* Theta = (const float*)d_in[2];
    const float* Bias  = (const float*)d_in[3];
    float* out = (float*)d_out;

    cudaFuncSetAttribute(pna_kernel, cudaFuncAttributeMaxDynamicSharedMemorySize,
                         SMEM_BYTES);

    deg_kernel<<<NN / 8, 256>>>(A);
    delta_kernel<<<1, 1024>>>();
    ahf_kernel<<<(NN * NN / 2 + 1023) / 1024, 1024>>>(A);
    xf_kernel<<<dim3(NN / 64, BB * PP), 256>>>(X);

    dim3 grid(NN / TM, BB * PP);
    pna_kernel<<<grid, THREADS, SMEM_BYTES>>>(Theta, Bias, out);
}

// round 12
// speedup vs baseline: 1.7377x; 1.3934x over previous
#include <cuda_runtime.h>
#include <cuda_fp16.h>
#include <cuda.h>
#include <math.h>
#include <stdint.h>

#define BB   4
#define CC   32
#define NN   2048
#define PP   12
#define OUTC 32
#define TM   128
#define KT   64
#define THREADS 512
#define EPSV 1e-5f
#define NEG_SLOPE 0.01f

// ---- smem layout ----
// stage (SW128, unpadded): A[128 rows][128 B] = 16384 ; F[256][128 B] = 32768
#define A_TILE_B  16384
#define SB_BYTES  49152
#define NBUF      4
#define MBAR_OFF  196608                  // 4 ring buffers end here
#define SMEM_BYTES 196736
// epilogue regions (u32 offsets, reuse ring after mainloop)
#define ACCS     264                      // ACC f32 [128][264] @0 (135168 B)
#define FEAT_OFF 33792                    // feats fp16 [128][116 u32] (59392 B -> ends 194560)
#define FBS      116
#define THB_OFF  0                        // ThetaB staged after phase A (ACC dead)
#define D_OFF    12800                    // D f32 [128][100] (51200 B, after THB's 44544)

__device__ __align__(1024) __half g_ahf[(size_t)NN * NN];            // fp16 A
__device__ __align__(1024) __half g_fhf[(size_t)BB * PP * 256 * NN]; // fp16 features
__device__ float g_xp[(size_t)BB * PP * NN * CC];
__device__ float g_deg[NN];
__device__ float g_delta;

// ---------------------------------------------------------------------------
__device__ __forceinline__ uint32_t smem_u32(const void* p) {
    uint32_t a;
    asm("{ .reg .u64 t; cvta.to.shared.u64 t, %1; cvt.u32.u64 %0, t; }" : "=r"(a) : "l"(p));
    return a;
}
#define MBAR_INIT(a, n) \
    asm volatile("mbarrier.init.shared.b64 [%0], %1;" :: "r"(a), "r"(n) : "memory")
#define MBAR_EXPECT_TX(a, bytes) \
    asm volatile("mbarrier.arrive.expect_tx.shared.b64 _, [%0], %1;" :: "r"(a), "r"(bytes) : "memory")
#define MBAR_WAIT(a, ph) do { \
    asm volatile("{\n\t.reg .pred P1;\n\tWL_%=:\n\t" \
        "mbarrier.try_wait.parity.acquire.cta.shared::cta.b64 P1, [%0], %1, 0x989680;\n\t" \
        "@P1 bra.uni WD_%=;\n\tbra.uni WL_%=;\n\tWD_%=:\n\t}" \
        :: "r"(a), "r"(ph) : "memory"); } while (0)
#define TMA_LOAD_2D(saddr, map, cx, cy, mbar) \
    asm volatile("cp.async.bulk.tensor.2d.shared::cta.global.tile.mbarrier::complete_tx::bytes " \
        "[%0], [%1, {%2, %3}], [%4];" \
        :: "r"((uint32_t)(saddr)), "l"(map), "r"((int)(cx)), "r"((int)(cy)), \
           "r"((uint32_t)(mbar)) : "memory")

__device__ __forceinline__ void ldsm_x4(uint32_t r[4], uint32_t addr) {
    asm volatile("ldmatrix.sync.aligned.m8n8.x4.shared.b16 {%0,%1,%2,%3}, [%4];"
        : "=r"(r[0]), "=r"(r[1]), "=r"(r[2]), "=r"(r[3]) : "r"(addr));
}
__device__ __forceinline__ void mma_f16(float c[4], const uint32_t a[4],
                                        const uint32_t b0, const uint32_t b1) {
    asm volatile(
        "mma.sync.aligned.m16n8k16.row.col.f32.f16.f16.f32 "
        "{%0,%1,%2,%3}, {%4,%5,%6,%7}, {%8,%9}, {%0,%1,%2,%3};"
        : "+f"(c[0]), "+f"(c[1]), "+f"(c[2]), "+f"(c[3])
        : "r"(a[0]), "r"(a[1]), "r"(a[2]), "r"(a[3]), "r"(b0), "r"(b1));
}
__device__ __forceinline__ uint32_t pack_h2(float lo, float hi) {
    __half2 h = __floats2half2_rn(lo, hi);
    return *reinterpret_cast<uint32_t*>(&h);
}

// ---------------------------------------------------------------------------
__global__ void deg_kernel(const float* __restrict__ A) {
    int row  = blockIdx.x * (blockDim.x >> 5) + (threadIdx.x >> 5);
    int lane = threadIdx.x & 31;
    const float* r = A + (size_t)row * NN;
    float s = 0.f;
    for (int j = lane; j < NN; j += 32) s += r[j];
    #pragma unroll
    for (int o = 16; o; o >>= 1) s += __shfl_xor_sync(0xffffffffu, s, o);
    if (lane == 0) g_deg[row] = s;
}

__global__ void delta_kernel() {
    __shared__ float red[32];
    int tid = threadIdx.x;
    float s = 0.f;
    for (int i = tid; i < NN; i += blockDim.x) s += logf(g_deg[i] + 1.f);
    #pragma unroll
    for (int o = 16; o; o >>= 1) s += __shfl_xor_sync(0xffffffffu, s, o);
    if ((tid & 31) == 0) red[tid >> 5] = s;
    __syncthreads();
    if (tid < 32) {
        float v = (tid < (int)(blockDim.x >> 5)) ? red[tid] : 0.f;
        #pragma unroll
        for (int o = 16; o; o >>= 1) v += __shfl_xor_sync(0xffffffffu, v, o);
        if (tid == 0) g_delta = v / (float)NN;
    }
}

__global__ void ahf_kernel(const float* __restrict__ A) {
    int idx = blockIdx.x * blockDim.x + threadIdx.x;
    if (idx >= NN * NN / 2) return;
    float2 v = reinterpret_cast<const float2*>(A)[idx];
    reinterpret_cast<uint32_t*>(g_ahf)[idx] = pack_h2(v.x, v.y);
}

// fused: transpose X -> g_xp AND build fp16 feature planes g_fhf
__global__ void xf_kernel(const float* __restrict__ X) {
    int bp = blockIdx.y, j0 = blockIdx.x * 64;
    int b = bp / PP, p = bp % PP;
    int t = threadIdx.x;   // 256
    int jp = t & 31;
    int chb = t >> 5;
    uint32_t* dst = reinterpret_cast<uint32_t*>(g_fhf);
    float* xpd = g_xp + (size_t)bp * NN * CC;
    #pragma unroll
    for (int it = 0; it < 4; it++) {
        int ch = chb * 4 + it;
        int j = j0 + 2 * jp;
        float x0 = X[(((size_t)b * CC + ch) * NN + j) * PP + p];
        float x1 = X[(((size_t)b * CC + ch) * NN + j + 1) * PP + p];
        xpd[(size_t)j * CC + ch]       = x0;
        xpd[(size_t)(j + 1) * CC + ch] = x1;
        float a2 = x0 * x0, b2 = x1 * x1;
        float e0 = expf(x0), e1 = expf(x1);
        float n0 = expf(-x0), n1 = expf(-x1);
        size_t base = (((size_t)bp * 256 + ch) * NN + j0) / 2 + jp;
        const size_t G = (size_t)32 * NN / 2;
        dst[base + 0 * G] = pack_h2(x0, x1);
        dst[base + 1 * G] = pack_h2(a2, b2);
        dst[base + 2 * G] = pack_h2(a2 * x0, b2 * x1);
        dst[base + 3 * G] = pack_h2(a2 * a2, b2 * b2);
        dst[base + 4 * G] = pack_h2(x0 * e0, x1 * e1);
        dst[base + 5 * G] = pack_h2(e0, e1);
        dst[base + 6 * G] = pack_h2(x0 * n0, x1 * n1);
        dst[base + 7 * G] = pack_h2(n0, n1);
    }
}

// ---------------------------------------------------------------------------
__global__ __launch_bounds__(THREADS, 1)
void pna_kernel(const __grid_constant__ CUtensorMap a_map,
                const __grid_constant__ CUtensorMap f_map,
                const float* __restrict__ Theta, const float* __restrict__ Bias,
                float* __restrict__ out) {
    extern __shared__ uint32_t smu[];
    const uint32_t sbase = smem_u32(smu);
    const uint32_t mbar0 = sbase + MBAR_OFF;

    const int tid = threadIdx.x, lane = tid & 31, wid = tid >> 5;
    const int lq = lane >> 2, lr = lane & 3;
    const int wm = wid >> 2, wn = wid & 3;      // 4x4 warps, warp tile 32x64
    const int bp = blockIdx.y, i0 = blockIdx.x * TM;
    const int b = bp / PP, p = bp % PP;

    // mbarrier init
    if (tid == 0) {
        #pragma unroll
        for (int i = 0; i < NBUF; i++) MBAR_INIT(mbar0 + 8 * i, 1);
    }
    __syncthreads();

    #define ISSUE(s) do {                                                     \
        int _bf = (s) & 3;                                                    \
        uint32_t _mb = mbar0 + 8 * _bf;                                       \
        uint32_t _sb = sbase + _bf * SB_BYTES;                                \
        MBAR_EXPECT_TX(_mb, SB_BYTES);                                        \
        TMA_LOAD_2D(_sb, &a_map, (s) * KT, i0, _mb);                          \
        TMA_LOAD_2D(_sb + A_TILE_B, &f_map, (s) * KT, bp * 256, _mb);         \
    } while (0)

    // ldmatrix swizzled (SW128, 128B rows) per-lane constants
    const int rowA = wm * 32 + (lane & 7) + ((lane >> 3) & 1) * 8;
    const uint32_t xorA = (uint32_t)((rowA & 7) << 4);
    const uint32_t colA = (uint32_t)(((lane >> 4) & 1) * 16);
    const uint32_t aoffb = (uint32_t)(rowA * 128);
    const int rowB = wn * 64 + (lane & 7) + ((lane >> 4) & 1) * 8;
    const uint32_t xorB = (uint32_t)((rowB & 7) << 4);
    const uint32_t colB = (uint32_t)(((lane >> 3) & 1) * 16);
    const uint32_t boffb = (uint32_t)(A_TILE_B + rowB * 128);

    float acc[2][8][4];
    #pragma unroll
    for (int mt = 0; mt < 2; mt++)
        #pragma unroll
        for (int nt = 0; nt < 8; nt++)
            #pragma unroll
            for (int j = 0; j < 4; j++) acc[mt][nt][j] = 0.f;

    if (tid == 0) { ISSUE(0); ISSUE(1); ISSUE(2); }

    const int NST = NN / KT;   // 32
    for (int s = 0; s < NST; s++) {
        MBAR_WAIT(mbar0 + 8 * (s & 3), (s >> 2) & 1);
        __syncthreads();                       // all warps done with stage s-1
        if (tid == 0 && s + 3 < NST) ISSUE(s + 3);

        const uint32_t stg = sbase + (uint32_t)((s & 3) * SB_BYTES);
        #pragma unroll
        for (int kb = 0; kb < 4; kb++) {
            const uint32_t ac = ((uint32_t)(kb * 32) + colA) ^ xorA;
            const uint32_t bc = ((uint32_t)(kb * 32) + colB) ^ xorB;
            uint32_t af[2][4], bf[4][4];
            #pragma unroll
            for (int mt = 0; mt < 2; mt++)
                ldsm_x4(af[mt], stg + aoffb + mt * 2048 + ac);
            #pragma unroll
            for (int ntp = 0; ntp < 4; ntp++)
                ldsm_x4(bf[ntp], stg + boffb + ntp * 2048 + bc);
            #pragma unroll
            for (int mt = 0; mt < 2; mt++)
                #pragma unroll
                for (int nt = 0; nt < 8; nt++)
                    mma_f16(acc[mt][nt], af[mt], bf[nt >> 1][(nt & 1) * 2],
                            bf[nt >> 1][(nt & 1) * 2 + 1]);
        }
    }
    #undef ISSUE
    __syncthreads();   // all MMAs done before epilogue reuses the ring

    // ---- spill ALL accumulators to ACC[128][264] f32 ----
    float* ACCf = reinterpret_cast<float*>(smu);
    #pragma unroll
    for (int mt = 0; mt < 2; mt++) {
        int r = wm * 32 + mt * 16 + lq;
        #pragma unroll
        for (int nt = 0; nt < 8; nt++) {
            int c = wn * 64 + nt * 8 + lr * 2;
            float* a = acc[mt][nt];
            ACCf[r * ACCS + c]           = a[0];
            ACCf[r * ACCS + c + 1]       = a[1];
            ACCf[(r + 8) * ACCS + c]     = a[2];
            ACCf[(r + 8) * ACCS + c + 1] = a[3];
        }
    }
    __syncthreads();

    // ---- phase A: aggregators -> feats fp16 (single pass, 128 rows) ----
    __half* Fbh = reinterpret_cast<__half*>(smu + FEAT_OFF);
    const float* xp = g_xp + (size_t)bp * NN * CC;
    for (int e = tid; e < TM * 32; e += THREADS) {
        int il = e >> 5, ch = e & 31;
        const float* row = &ACCf[il * ACCS];
        float S1  = row[ch],       S2  = row[32 + ch];
        float S3  = row[64 + ch],  S4  = row[96 + ch];
        float SXP = row[128 + ch], SEP = row[160 + ch];
        float SXN = row[192 + ch], SEN = row[224 + ch];

        int i = i0 + il;
        float x    = xp[(size_t)i * CC + ch];
        float dg   = g_deg[i];
        float dinv = 1.f / fmaxf(dg, EPSV);
        float m1 = S1 * dinv, m2 = S2 * dinv, m3 = S3 * dinv, m4 = S4 * dinv;
        float smax = SXP / (SEP + EPSV);
        float smin = SXN / (SEN + EPSV);
        float var  = fmaxf(m2 - m1 * m1, 0.f);
        float stdv = sqrtf(var + EPSV);
        float x2 = x * x, x3 = x2 * x, x4 = x2 * x2;
        float dist = x2 - 2.f * x * m1 + m2;
        float ed2  = x4 - 4.f * x3 * m1 + 6.f * x2 * m2 - 4.f * x * m3 + m4;
        float dstd = sqrtf(fmaxf(ed2 - dist * dist, 0.f) + EPSV);

        __half* fr = Fbh + (size_t)il * (2 * FBS);
        fr[0 * 32 + ch] = __float2half(smin);
        fr[1 * 32 + ch] = __float2half(smax);
        fr[2 * 32 + ch] = __float2half(m1);
        fr[3 * 32 + ch] = __float2half(stdv);
        fr[4 * 32 + ch] = __float2half(var);
        fr[5 * 32 + ch] = __float2half(dist);
        fr[6 * 32 + ch] = __float2half(dstd);
    }
    __syncthreads();

    // ---- stage ThetaB [96 n][112 k-pairs] fp16 into dead ACC region ----
    for (int idx = tid; idx < 96 * 112; idx += THREADS) {
        int p2 = idx / 96, n = idx % 96;
        int q = n >> 5, o = n & 31;
        float f0 = Theta[(size_t)(224 * q + 2 * p2) * OUTC + o];
        float f1 = Theta[(size_t)(224 * q + 2 * p2 + 1) * OUTC + o];
        smu[THB_OFF + n * FBS + p2] = pack_h2(f0, f1);
    }
    __syncthreads();

    // ---- GEMM2 (fp16): D[128][96] = feats[128x224] @ ThetaB^T ----
    {
        const uint32_t* Fb = smu + FEAT_OFF;
        const uint32_t* Tb = smu + THB_OFF;
        const int wm2 = wid >> 1, wn2 = wid & 1;
        float a2[6][4];
        #pragma unroll
        for (int nt = 0; nt < 6; nt++)
            #pragma unroll
            for (int j = 0; j < 4; j++) a2[nt][j] = 0.f;

        #pragma unroll 2
        for (int kb = 0; kb < 14; kb++) {
            uint32_t af[4], bfv[6][2];
            int r = (wm2 * 16 + lq) * FBS + kb * 8 + lr;
            af[0] = Fb[r];
            af[1] = Fb[r + 8 * FBS];
            af[2] = Fb[r + 4];
            af[3] = Fb[r + 8 * FBS + 4];
            #pragma unroll
            for (int nt = 0; nt < 6; nt++) {
                int c = (wn2 * 48 + nt * 8 + lq) * FBS + kb * 8 + lr;
                bfv[nt][0] = Tb[c];
                bfv[nt][1] = Tb[c + 4];
            }
            #pragma unroll
            for (int nt = 0; nt < 6; nt++)
                mma_f16(a2[nt], af, bfv[nt][0], bfv[nt][1]);
        }
        __syncthreads();
        float* D = reinterpret_cast<float*>(smu + D_OFF);
        int r = wm2 * 16 + lq;
        #pragma unroll
        for (int nt = 0; nt < 6; nt++) {
            int c = wn2 * 48 + nt * 8 + 2 * lr;
            D[r * 100 + c]           = a2[nt][0];
            D[r * 100 + c + 1]       = a2[nt][1];
            D[(r + 8) * 100 + c]     = a2[nt][2];
            D[(r + 8) * 100 + c + 1] = a2[nt][3];
        }
        __syncthreads();

        int i = tid >> 2;
        int ob = (tid & 3) * 8;
        float dg = g_deg[i0 + i];
        float sv = logf(dg + 1.f) / g_delta;
        float iv = 1.f / fmaxf(sv, EPSV);
        #pragma unroll
        for (int k = 0; k < 8; k++) {
            int o = ob + k;
            float v = D[i * 100 + o] + sv * D[i * 100 + 32 + o] +
                      iv * D[i * 100 + 64 + o] + Bias[o];
            v = v > 0.f ? v : NEG_SLOPE * v;
            out[(((size_t)b * OUTC + o) * NN + (i0 + i)) * PP + p] = v;
        }
    }
}

// ---------------------------------------------------------------------------
typedef CUresult (*PFN_encodeTiled)(CUtensorMap*, CUtensorMapDataType, cuuint32_t,
                                    void*, const cuuint64_t*, const cuuint64_t*,
                                    const cuuint32_t*, const cuuint32_t*,
                                    CUtensorMapInterleave, CUtensorMapSwizzle,
                                    CUtensorMapL2promotion, CUtensorMapFloatOOBfill);

extern "C" void kernel_launch(void* const* d_in, const int* in_sizes, int n_in,
                              void* d_out, int out_size) {
    const float* X     = (const float*)d_in[0];
    const float* A     = (const float*)d_in[1];
    const float* Theta = (const float*)d_in[2];
    const float* Bias  = (const float*)d_in[3];
    float* out = (float*)d_out;

    void* fn = nullptr;
    cudaDriverEntryPointQueryResult qr;
#if CUDART_VERSION >= 12050
    cudaGetDriverEntryPointByVersion("cuTensorMapEncodeTiled", &fn, 12000,
                                     cudaEnableDefault, &qr);
#else
    cudaGetDriverEntryPoint("cuTensorMapEncodeTiled", &fn, cudaEnableDefault, &qr);
#endif
    PFN_encodeTiled encode = (PFN_encodeTiled)fn;

    void *dA = nullptr, *dF = nullptr;
    cudaGetSymbolAddress(&dA, g_ahf);
    cudaGetSymbolAddress(&dF, g_fhf);

    CUtensorMap a_map, f_map;
    {
        cuuint64_t dims[2]    = {NN, NN};
        cuuint64_t strides[1] = {(cuuint64_t)NN * 2};
        cuuint32_t box[2]     = {KT, 128};
        cuuint32_t es[2]      = {1, 1};
        encode(&a_map, CU_TENSOR_MAP_DATA_TYPE_FLOAT16, 2, dA, dims, strides, box, es,
               CU_TENSOR_MAP_INTERLEAVE_NONE, CU_TENSOR_MAP_SWIZZLE_128B,
               CU_TENSOR_MAP_L2_PROMOTION_L2_128B, CU_TENSOR_MAP_FLOAT_OOB_FILL_NONE);
    }
    {
        cuuint64_t dims[2]    = {NN, (cuuint64_t)BB * PP * 256};
        cuuint64_t strides[1] = {(cuuint64_t)NN * 2};
        cuuint32_t box[2]     = {KT, 256};
        cuuint32_t es[2]      = {1, 1};
        encode(&f_map, CU_TENSOR_MAP_DATA_TYPE_FLOAT16, 2, dF, dims, strides, box, es,
               CU_TENSOR_MAP_INTERLEAVE_NONE, CU_TENSOR_MAP_SWIZZLE_128B,
               CU_TENSOR_MAP_L2_PROMOTION_L2_128B, CU_TENSOR_MAP_FLOAT_OOB_FILL_NONE);
    }

    cudaFuncSetAttribute(pna_kernel, cudaFuncAttributeMaxDynamicSharedMemorySize,
                         SMEM_BYTES);

    deg_kernel<<<NN / 8, 256>>>(A);
    delta_kernel<<<1, 1024>>>();
    ahf_kernel<<<(NN * NN / 2 + 1023) / 1024, 1024>>>(A);
    xf_kernel<<<dim3(NN / 64, BB * PP), 256>>>(X);

    dim3 grid(NN / TM, BB * PP);
    pna_kernel<<<grid, THREADS, SMEM_BYTES>>>(a_map, f_map, Theta, Bias, out);
}

// round 13
// speedup vs baseline: 1.8382x; 1.0578x over previous
#include <cuda_runtime.h>
#include <cuda_fp16.h>
#include <cuda.h>
#include <math.h>
#include <stdint.h>

#define BB   4
#define CC   32
#define NN   2048
#define PP   12
#define OUTC 32
#define TM   128
#define KT   64
#define THREADS 512
#define EPSV 1e-5f
#define NEG_SLOPE 0.01f

// ---- pna smem layout ----
#define A_TILE_B  16384
#define SB_BYTES  49152
#define NBUF      4
#define MBAR_OFF  196608
#define SMEM_BYTES 196736
#define ACCS     264
#define FEAT_OFF 33792
#define FBS      116
#define THB_OFF  0
#define D_OFF    12800

__device__ __align__(1024) __half g_ahf[(size_t)NN * NN];
__device__ __align__(1024) __half g_fhf[(size_t)BB * PP * 256 * NN];
__device__ float g_xp[(size_t)BB * PP * NN * CC];
__device__ float g_deg[NN];
__device__ float g_delta;

// ---------------------------------------------------------------------------
__device__ __forceinline__ uint32_t smem_u32(const void* p) {
    uint32_t a;
    asm("{ .reg .u64 t; cvta.to.shared.u64 t, %1; cvt.u32.u64 %0, t; }" : "=r"(a) : "l"(p));
    return a;
}
#define MBAR_INIT(a, n) \
    asm volatile("mbarrier.init.shared.b64 [%0], %1;" :: "r"(a), "r"(n) : "memory")
#define MBAR_EXPECT_TX(a, bytes) \
    asm volatile("mbarrier.arrive.expect_tx.shared.b64 _, [%0], %1;" :: "r"(a), "r"(bytes) : "memory")
#define MBAR_WAIT(a, ph) do { \
    asm volatile("{\n\t.reg .pred P1;\n\tWL_%=:\n\t" \
        "mbarrier.try_wait.parity.acquire.cta.shared::cta.b64 P1, [%0], %1, 0x989680;\n\t" \
        "@P1 bra.uni WD_%=;\n\tbra.uni WL_%=;\n\tWD_%=:\n\t}" \
        :: "r"(a), "r"(ph) : "memory"); } while (0)
#define TMA_LOAD_2D(saddr, map, cx, cy, mbar) \
    asm volatile("cp.async.bulk.tensor.2d.shared::cta.global.tile.mbarrier::complete_tx::bytes " \
        "[%0], [%1, {%2, %3}], [%4];" \
        :: "r"((uint32_t)(saddr)), "l"(map), "r"((int)(cx)), "r"((int)(cy)), \
           "r"((uint32_t)(mbar)) : "memory")

__device__ __forceinline__ void ldsm_x4(uint32_t r[4], uint32_t addr) {
    asm volatile("ldmatrix.sync.aligned.m8n8.x4.shared.b16 {%0,%1,%2,%3}, [%4];"
        : "=r"(r[0]), "=r"(r[1]), "=r"(r[2]), "=r"(r[3]) : "r"(addr));
}
__device__ __forceinline__ void mma_f16(float c[4], const uint32_t a[4],
                                        const uint32_t b0, const uint32_t b1) {
    asm volatile(
        "mma.sync.aligned.m16n8k16.row.col.f32.f16.f16.f32 "
        "{%0,%1,%2,%3}, {%4,%5,%6,%7}, {%8,%9}, {%0,%1,%2,%3};"
        : "+f"(c[0]), "+f"(c[1]), "+f"(c[2]), "+f"(c[3])
        : "r"(a[0]), "r"(a[1]), "r"(a[2]), "r"(a[3]), "r"(b0), "r"(b1));
}
__device__ __forceinline__ uint32_t pack_h2(float lo, float hi) {
    __half2 h = __floats2half2_rn(lo, hi);
    return *reinterpret_cast<uint32_t*>(&h);
}

// ---------------------------------------------------------------------------
// fused: A -> fp16 conversion + row-degree (warp per row)
__global__ void ahf_deg_kernel(const float* __restrict__ A) {
    int row  = blockIdx.x * 8 + (threadIdx.x >> 5);
    int lane = threadIdx.x & 31;
    const float4* src = reinterpret_cast<const float4*>(A + (size_t)row * NN);
    uint32_t* dst = reinterpret_cast<uint32_t*>(g_ahf) + (size_t)row * (NN / 2);
    float s = 0.f;
    #pragma unroll
    for (int k = 0; k < 16; k++) {
        float4 v = src[lane + 32 * k];
        s += (v.x + v.y) + (v.z + v.w);
        dst[2 * (lane + 32 * k)]     = pack_h2(v.x, v.y);
        dst[2 * (lane + 32 * k) + 1] = pack_h2(v.z, v.w);
    }
    #pragma unroll
    for (int o = 16; o; o >>= 1) s += __shfl_xor_sync(0xffffffffu, s, o);
    if (lane == 0) g_deg[row] = s;
}

__global__ void delta_kernel() {
    __shared__ float red[32];
    int tid = threadIdx.x;
    float s = 0.f;
    for (int i = tid; i < NN; i += blockDim.x) s += logf(g_deg[i] + 1.f);
    #pragma unroll
    for (int o = 16; o; o >>= 1) s += __shfl_xor_sync(0xffffffffu, s, o);
    if ((tid & 31) == 0) red[tid >> 5] = s;
    __syncthreads();
    if (tid < 32) {
        float v = (tid < (int)(blockDim.x >> 5)) ? red[tid] : 0.f;
        #pragma unroll
        for (int o = 16; o; o >>= 1) v += __shfl_xor_sync(0xffffffffu, v, o);
        if (tid == 0) g_delta = v / (float)NN;
    }
}

// coalesced: transpose X -> g_xp AND build fp16 feature planes g_fhf
// block = (j-slab of 32, b); smem tile sx[ch][j*12+p], row stride 387 (≡3 mod 32)
#define SXS 387
__global__ void xf_kernel(const float* __restrict__ X) {
    extern __shared__ float sx[];
    const int b  = blockIdx.y;
    const int j0 = blockIdx.x * 32;
    const int t  = threadIdx.x;       // 256
    const int lane = t & 31, w = t >> 5;

    // phase 1: coalesced load. per ch: 384 contiguous floats.
    #pragma unroll
    for (int i = 0; i < 48; i++) {
        int e = t + 256 * i;          // 0..12287
        int ch = e / 384, rem = e - ch * 384;
        sx[ch * SXS + rem] = X[((size_t)(b * CC + ch) * NN + j0) * PP + rem];
    }
    __syncthreads();

    // phase 2: g_xp[bp][j][ch] — warp-coalesced 128B rows, conflict-free LDS
    #pragma unroll
    for (int p = 0; p < PP; p++) {
        int bp = b * PP + p;
        float* xpd = g_xp + ((size_t)bp * NN + j0) * CC;
        #pragma unroll
        for (int i = 0; i < 4; i++) {
            int e = t + 256 * i;      // 0..1023
            int j = e >> 5, ch = e & 31;
            xpd[j * CC + ch] = sx[ch * SXS + j * 12 + p];
        }
    }

    // phase 3: features — lanes over j (64B coalesced fhf writes)
    __half* fh = reinterpret_cast<__half*>(g_fhf);
    #pragma unroll
    for (int i = 0; i < 4; i++) {
        int ch = w + 8 * i;
        #pragma unroll
        for (int p = 0; p < PP; p++) {
            int bp = b * PP + p;
            float x = sx[ch * SXS + lane * 12 + p];
            float x2 = x * x;
            float ep = expf(x), en = expf(-x);
            size_t base = (((size_t)bp * 256 + ch) * NN + j0) + lane;
            const size_t G = (size_t)32 * NN;
            fh[base + 0 * G] = __float2half(x);
            fh[base + 1 * G] = __float2half(x2);
            fh[base + 2 * G] = __float2half(x2 * x);
            fh[base + 3 * G] = __float2half(x2 * x2);
            fh[base + 4 * G] = __float2half(x * ep);
            fh[base + 5 * G] = __float2half(ep);
            fh[base + 6 * G] = __float2half(x * en);
            fh[base + 7 * G] = __float2half(en);
        }
    }
}

// ---------------------------------------------------------------------------
__global__ __launch_bounds__(THREADS, 1)
void pna_kernel(const __grid_constant__ CUtensorMap a_map,
                const __grid_constant__ CUtensorMap f_map,
                const float* __restrict__ Theta, const float* __restrict__ Bias,
                float* __restrict__ out) {
    extern __shared__ uint32_t smu[];
    const uint32_t sbase = smem_u32(smu);
    const uint32_t mbar0 = sbase + MBAR_OFF;

    const int tid = threadIdx.x, lane = tid & 31, wid = tid >> 5;
    const int lq = lane >> 2, lr = lane & 3;
    const int wm = wid >> 2, wn = wid & 3;
    const int bp = blockIdx.y, i0 = blockIdx.x * TM;
    const int b = bp / PP, p = bp % PP;

    if (tid == 0) {
        #pragma unroll
        for (int i = 0; i < NBUF; i++) MBAR_INIT(mbar0 + 8 * i, 1);
    }
    __syncthreads();

    #define ISSUE(s) do {                                                     \
        int _bf = (s) & 3;                                                    \
        uint32_t _mb = mbar0 + 8 * _bf;                                       \
        uint32_t _sb = sbase + _bf * SB_BYTES;                                \
        MBAR_EXPECT_TX(_mb, SB_BYTES);                                        \
        TMA_LOAD_2D(_sb, &a_map, (s) * KT, i0, _mb);                          \
        TMA_LOAD_2D(_sb + A_TILE_B, &f_map, (s) * KT, bp * 256, _mb);         \
    } while (0)

    const int rowA = wm * 32 + (lane & 7) + ((lane >> 3) & 1) * 8;
    const uint32_t xorA = (uint32_t)((rowA & 7) << 4);
    const uint32_t colA = (uint32_t)(((lane >> 4) & 1) * 16);
    const uint32_t aoffb = (uint32_t)(rowA * 128);
    const int rowB = wn * 64 + (lane & 7) + ((lane >> 4) & 1) * 8;
    const uint32_t xorB = (uint32_t)((rowB & 7) << 4);
    const uint32_t colB = (uint32_t)(((lane >> 3) & 1) * 16);
    const uint32_t boffb = (uint32_t)(A_TILE_B + rowB * 128);

    float acc[2][8][4];
    #pragma unroll
    for (int mt = 0; mt < 2; mt++)
        #pragma unroll
        for (int nt = 0; nt < 8; nt++)
            #pragma unroll
            for (int j = 0; j < 4; j++) acc[mt][nt][j] = 0.f;

    if (tid == 0) { ISSUE(0); ISSUE(1); ISSUE(2); }

    const int NST = NN / KT;   // 32
    for (int s = 0; s < NST; s++) {
        MBAR_WAIT(mbar0 + 8 * (s & 3), (s >> 2) & 1);
        __syncthreads();
        if (tid == 0 && s + 3 < NST) ISSUE(s + 3);

        const uint32_t stg = sbase + (uint32_t)((s & 3) * SB_BYTES);
        #pragma unroll
        for (int kb = 0; kb < 4; kb++) {
            const uint32_t ac = ((uint32_t)(kb * 32) + colA) ^ xorA;
            const uint32_t bc = ((uint32_t)(kb * 32) + colB) ^ xorB;
            uint32_t af[2][4], bf[4][4];
            #pragma unroll
            for (int mt = 0; mt < 2; mt++)
                ldsm_x4(af[mt], stg + aoffb + mt * 2048 + ac);
            #pragma unroll
            for (int ntp = 0; ntp < 4; ntp++)
                ldsm_x4(bf[ntp], stg + boffb + ntp * 2048 + bc);
            #pragma unroll
            for (int mt = 0; mt < 2; mt++)
                #pragma unroll
                for (int nt = 0; nt < 8; nt++)
                    mma_f16(acc[mt][nt], af[mt], bf[nt >> 1][(nt & 1) * 2],
                            bf[nt >> 1][(nt & 1) * 2 + 1]);
        }
    }
    #undef ISSUE
    __syncthreads();

    // ---- spill accumulators to ACC[128][264] f32 ----
    float* ACCf = reinterpret_cast<float*>(smu);
    #pragma unroll
    for (int mt = 0; mt < 2; mt++) {
        int r = wm * 32 + mt * 16 + lq;
        #pragma unroll
        for (int nt = 0; nt < 8; nt++) {
            int c = wn * 64 + nt * 8 + lr * 2;
            float* a = acc[mt][nt];
            ACCf[r * ACCS + c]           = a[0];
            ACCf[r * ACCS + c + 1]       = a[1];
            ACCf[(r + 8) * ACCS + c]     = a[2];
            ACCf[(r + 8) * ACCS + c + 1] = a[3];
        }
    }
    __syncthreads();

    // ---- phase A: aggregators -> feats fp16 ----
    __half* Fbh = reinterpret_cast<__half*>(smu + FEAT_OFF);
    const float* xp = g_xp + (size_t)bp * NN * CC;
    for (int e = tid; e < TM * 32; e += THREADS) {
        int il = e >> 5, ch = e & 31;
        const float* row = &ACCf[il * ACCS];
        float S1  = row[ch],       S2  = row[32 + ch];
        float S3  = row[64 + ch],  S4  = row[96 + ch];
        float SXP = row[128 + ch], SEP = row[160 + ch];
        float SXN = row[192 + ch], SEN = row[224 + ch];

        int i = i0 + il;
        float x    = xp[(size_t)i * CC + ch];
        float dg   = g_deg[i];
        float dinv = 1.f / fmaxf(dg, EPSV);
        float m1 = S1 * dinv, m2 = S2 * dinv, m3 = S3 * dinv, m4 = S4 * dinv;
        float smax = SXP / (SEP + EPSV);
        float smin = SXN / (SEN + EPSV);
        float var  = fmaxf(m2 - m1 * m1, 0.f);
        float stdv = sqrtf(var + EPSV);
        float x2 = x * x, x3 = x2 * x, x4 = x2 * x2;
        float dist = x2 - 2.f * x * m1 + m2;
        float ed2  = x4 - 4.f * x3 * m1 + 6.f * x2 * m2 - 4.f * x * m3 + m4;
        float dstd = sqrtf(fmaxf(ed2 - dist * dist, 0.f) + EPSV);

        __half* fr = Fbh + (size_t)il * (2 * FBS);
        fr[0 * 32 + ch] = __float2half(smin);
        fr[1 * 32 + ch] = __float2half(smax);
        fr[2 * 32 + ch] = __float2half(m1);
        fr[3 * 32 + ch] = __float2half(stdv);
        fr[4 * 32 + ch] = __float2half(var);
        fr[5 * 32 + ch] = __float2half(dist);
        fr[6 * 32 + ch] = __float2half(dstd);
    }
    __syncthreads();

    // ---- stage ThetaB fp16 into dead ACC region ----
    for (int idx = tid; idx < 96 * 112; idx += THREADS) {
        int p2 = idx / 96, n = idx % 96;
        int q = n >> 5, o = n & 31;
        float f0 = Theta[(size_t)(224 * q + 2 * p2) * OUTC + o];
        float f1 = Theta[(size_t)(224 * q + 2 * p2 + 1) * OUTC + o];
        smu[THB_OFF + n * FBS + p2] = pack_h2(f0, f1);
    }
    __syncthreads();

    // ---- GEMM2 (fp16): D[128][96] = feats[128x224] @ ThetaB^T ----
    {
        const uint32_t* Fb = smu + FEAT_OFF;
        const uint32_t* Tb = smu + THB_OFF;
        const int wm2 = wid >> 1, wn2 = wid & 1;
        float a2[6][4];
        #pragma unroll
        for (int nt = 0; nt < 6; nt++)
            #pragma unroll
            for (int j = 0; j < 4; j++) a2[nt][j] = 0.f;

        #pragma unroll 2
        for (int kb = 0; kb < 14; kb++) {
            uint32_t af[4], bfv[6][2];
            int r = (wm2 * 16 + lq) * FBS + kb * 8 + lr;
            af[0] = Fb[r];
            af[1] = Fb[r + 8 * FBS];
            af[2] = Fb[r + 4];
            af[3] = Fb[r + 8 * FBS + 4];
            #pragma unroll
            for (int nt = 0; nt < 6; nt++) {
                int c = (wn2 * 48 + nt * 8 + lq) * FBS + kb * 8 + lr;
                bfv[nt][0] = Tb[c];
                bfv[nt][1] = Tb[c + 4];
            }
            #pragma unroll
            for (int nt = 0; nt < 6; nt++)
                mma_f16(a2[nt], af, bfv[nt][0], bfv[nt][1]);
        }
        __syncthreads();
        float* D = reinterpret_cast<float*>(smu + D_OFF);
        int r = wm2 * 16 + lq;
        #pragma unroll
        for (int nt = 0; nt < 6; nt++) {
            int c = wn2 * 48 + nt * 8 + 2 * lr;
            D[r * 100 + c]           = a2[nt][0];
            D[r * 100 + c + 1]       = a2[nt][1];
            D[(r + 8) * 100 + c]     = a2[nt][2];
            D[(r + 8) * 100 + c + 1] = a2[nt][3];
        }
        __syncthreads();

        int i = tid >> 2;
        int ob = (tid & 3) * 8;
        float dg = g_deg[i0 + i];
        float sv = logf(dg + 1.f) / g_delta;
        float iv = 1.f / fmaxf(sv, EPSV);
        #pragma unroll
        for (int k = 0; k < 8; k++) {
            int o = ob + k;
            float v = D[i * 100 + o] + sv * D[i * 100 + 32 + o] +
                      iv * D[i * 100 + 64 + o] + Bias[o];
            v = v > 0.f ? v : NEG_SLOPE * v;
            out[(((size_t)b * OUTC + o) * NN + (i0 + i)) * PP + p] = v;
        }
    }
}

// ---------------------------------------------------------------------------
typedef CUresult (*PFN_encodeTiled)(CUtensorMap*, CUtensorMapDataType, cuuint32_t,
                                    void*, const cuuint64_t*, const cuuint64_t*,
                                    const cuuint32_t*, const cuuint32_t*,
                                    CUtensorMapInterleave, CUtensorMapSwizzle,
                                    CUtensorMapL2promotion, CUtensorMapFloatOOBfill);

extern "C" void kernel_launch(void* const* d_in, const int* in_sizes, int n_in,
                              void* d_out, int out_size) {
    const float* X     = (const float*)d_in[0];
    const float* A     = (const float*)d_in[1];
    const float* Theta = (const float*)d_in[2];
    const float* Bias  = (const float*)d_in[3];
    float* out = (float*)d_out;

    void* fn = nullptr;
    cudaDriverEntryPointQueryResult qr;
#if CUDART_VERSION >= 12050
    cudaGetDriverEntryPointByVersion("cuTensorMapEncodeTiled", &fn, 12000,
                                     cudaEnableDefault, &qr);
#else
    cudaGetDriverEntryPoint("cuTensorMapEncodeTiled", &fn, cudaEnableDefault, &qr);
#endif
    PFN_encodeTiled encode = (PFN_encodeTiled)fn;

    void *dA = nullptr, *dF = nullptr;
    cudaGetSymbolAddress(&dA, g_ahf);
    cudaGetSymbolAddress(&dF, g_fhf);

    CUtensorMap a_map, f_map;
    {
        cuuint64_t dims[2]    = {NN, NN};
        cuuint64_t strides[1] = {(cuuint64_t)NN * 2};
        cuuint32_t box[2]     = {KT, 128};
        cuuint32_t es[2]      = {1, 1};
        encode(&a_map, CU_TENSOR_MAP_DATA_TYPE_FLOAT16, 2, dA, dims, strides, box, es,
               CU_TENSOR_MAP_INTERLEAVE_NONE, CU_TENSOR_MAP_SWIZZLE_128B,
               CU_TENSOR_MAP_L2_PROMOTION_L2_128B, CU_TENSOR_MAP_FLOAT_OOB_FILL_NONE);
    }
    {
        cuuint64_t dims[2]    = {NN, (cuuint64_t)BB * PP * 256};
        cuuint64_t strides[1] = {(cuuint64_t)NN * 2};
        cuuint32_t box[2]     = {KT, 256};
        cuuint32_t es[2]      = {1, 1};
        encode(&f_map, CU_TENSOR_MAP_DATA_TYPE_FLOAT16, 2, dF, dims, strides, box, es,
               CU_TENSOR_MAP_INTERLEAVE_NONE, CU_TENSOR_MAP_SWIZZLE_128B,
               CU_TENSOR_MAP_L2_PROMOTION_L2_128B, CU_TENSOR_MAP_FLOAT_OOB_FILL_NONE);
    }

    cudaFuncSetAttribute(pna_kernel, cudaFuncAttributeMaxDynamicSharedMemorySize,
                         SMEM_BYTES);
    cudaFuncSetAttribute(xf_kernel, cudaFuncAttributeMaxDynamicSharedMemorySize,
                         CC * SXS * 4);

    ahf_deg_kernel<<<NN / 8, 256>>>(A);
    delta_kernel<<<1, 1024>>>();
    xf_kernel<<<dim3(NN / 32, BB), 256, CC * SXS * 4>>>(X);

    dim3 grid(NN / TM, BB * PP);
    pna_kernel<<<grid, THREADS, SMEM_BYTES>>>(a_map, f_map, Theta, Bias, out);
}

// round 14
// speedup vs baseline: 1.9282x; 1.0490x over previous
#include <cuda_runtime.h>
#include <cuda_fp16.h>
#include <cuda.h>
#include <math.h>
#include <stdint.h>

#define BB   4
#define CC   32
#define NN   2048
#define PP   12
#define OUTC 32
#define TM   128
#define KT   64
#define THREADS 512
#define EPSV 1e-5f
#define NEG_SLOPE 0.01f

// ---- pna smem layout ----
#define A_TILE_B  16384
#define SB_BYTES  49152
#define NBUF      4
#define MBAR_OFF  196608
#define SMEM_BYTES 196736
#define ACCS     264
#define FEAT_OFF 33792
#define FBS      116
#define THB_OFF  0
#define D_OFF    12800

__device__ __align__(1024) __half g_ahf[(size_t)NN * NN];
__device__ __align__(1024) __half g_fhf[(size_t)BB * PP * 256 * NN];
__device__ float g_xp[(size_t)BB * PP * NN * CC];
__device__ float g_deg[NN];
__device__ float g_delta;

// ---------------------------------------------------------------------------
__device__ __forceinline__ uint32_t smem_u32(const void* p) {
    uint32_t a;
    asm("{ .reg .u64 t; cvta.to.shared.u64 t, %1; cvt.u32.u64 %0, t; }" : "=r"(a) : "l"(p));
    return a;
}
#define MBAR_INIT(a, n) \
    asm volatile("mbarrier.init.shared.b64 [%0], %1;" :: "r"(a), "r"(n) : "memory")
#define MBAR_EXPECT_TX(a, bytes) \
    asm volatile("mbarrier.arrive.expect_tx.shared.b64 _, [%0], %1;" :: "r"(a), "r"(bytes) : "memory")
#define MBAR_WAIT(a, ph) do { \
    asm volatile("{\n\t.reg .pred P1;\n\tWL_%=:\n\t" \
        "mbarrier.try_wait.parity.acquire.cta.shared::cta.b64 P1, [%0], %1, 0x989680;\n\t" \
        "@P1 bra.uni WD_%=;\n\tbra.uni WL_%=;\n\tWD_%=:\n\t}" \
        :: "r"(a), "r"(ph) : "memory"); } while (0)
#define TMA_LOAD_2D(saddr, map, cx, cy, mbar) \
    asm volatile("cp.async.bulk.tensor.2d.shared::cta.global.tile.mbarrier::complete_tx::bytes " \
        "[%0], [%1, {%2, %3}], [%4];" \
        :: "r"((uint32_t)(saddr)), "l"(map), "r"((int)(cx)), "r"((int)(cy)), \
           "r"((uint32_t)(mbar)) : "memory")

__device__ __forceinline__ void ldsm_x4(uint32_t r[4], uint32_t addr) {
    asm volatile("ldmatrix.sync.aligned.m8n8.x4.shared.b16 {%0,%1,%2,%3}, [%4];"
        : "=r"(r[0]), "=r"(r[1]), "=r"(r[2]), "=r"(r[3]) : "r"(addr));
}
__device__ __forceinline__ void mma_f16(float c[4], const uint32_t a[4],
                                        const uint32_t b0, const uint32_t b1) {
    asm volatile(
        "mma.sync.aligned.m16n8k16.row.col.f32.f16.f16.f32 "
        "{%0,%1,%2,%3}, {%4,%5,%6,%7}, {%8,%9}, {%0,%1,%2,%3};"
        : "+f"(c[0]), "+f"(c[1]), "+f"(c[2]), "+f"(c[3])
        : "r"(a[0]), "r"(a[1]), "r"(a[2]), "r"(a[3]), "r"(b0), "r"(b1));
}
__device__ __forceinline__ uint32_t pack_h2(float lo, float hi) {
    __half2 h = __floats2half2_rn(lo, hi);
    return *reinterpret_cast<uint32_t*>(&h);
}

// ---------------------------------------------------------------------------
// fused: A -> fp16 conversion + row-degree (warp per row)
__global__ void ahf_deg_kernel(const float* __restrict__ A) {
    int row  = blockIdx.x * 8 + (threadIdx.x >> 5);
    int lane = threadIdx.x & 31;
    const float4* src = reinterpret_cast<const float4*>(A + (size_t)row * NN);
    uint32_t* dst = reinterpret_cast<uint32_t*>(g_ahf) + (size_t)row * (NN / 2);
    float s = 0.f;
    #pragma unroll
    for (int k = 0; k < 16; k++) {
        float4 v = src[lane + 32 * k];
        s += (v.x + v.y) + (v.z + v.w);
        dst[2 * (lane + 32 * k)]     = pack_h2(v.x, v.y);
        dst[2 * (lane + 32 * k) + 1] = pack_h2(v.z, v.w);
    }
    #pragma unroll
    for (int o = 16; o; o >>= 1) s += __shfl_xor_sync(0xffffffffu, s, o);
    if (lane == 0) g_deg[row] = s;
}

__global__ void delta_kernel() {
    __shared__ float red[32];
    int tid = threadIdx.x;
    float s = 0.f;
    for (int i = tid; i < NN; i += blockDim.x) s += logf(g_deg[i] + 1.f);
    #pragma unroll
    for (int o = 16; o; o >>= 1) s += __shfl_xor_sync(0xffffffffu, s, o);
    if ((tid & 31) == 0) red[tid >> 5] = s;
    __syncthreads();
    if (tid < 32) {
        float v = (tid < (int)(blockDim.x >> 5)) ? red[tid] : 0.f;
        #pragma unroll
        for (int o = 16; o; o >>= 1) v += __shfl_xor_sync(0xffffffffu, v, o);
        if (tid == 0) g_delta = v / (float)NN;
    }
}

// coalesced: transpose X -> g_xp AND build fp16 feature planes g_fhf
#define SXS 387
__global__ void xf_kernel(const float* __restrict__ X) {
    extern __shared__ float sx[];
    const int b  = blockIdx.y;
    const int j0 = blockIdx.x * 32;
    const int t  = threadIdx.x;       // 256
    const int lane = t & 31, w = t >> 5;

    #pragma unroll
    for (int i = 0; i < 48; i++) {
        int e = t + 256 * i;
        int ch = e / 384, rem = e - ch * 384;
        sx[ch * SXS + rem] = X[((size_t)(b * CC + ch) * NN + j0) * PP + rem];
    }
    __syncthreads();

    #pragma unroll
    for (int p = 0; p < PP; p++) {
        int bp = b * PP + p;
        float* xpd = g_xp + ((size_t)bp * NN + j0) * CC;
        #pragma unroll
        for (int i = 0; i < 4; i++) {
            int e = t + 256 * i;
            int j = e >> 5, ch = e & 31;
            xpd[j * CC + ch] = sx[ch * SXS + j * 12 + p];
        }
    }

    __half* fh = reinterpret_cast<__half*>(g_fhf);
    #pragma unroll
    for (int i = 0; i < 4; i++) {
        int ch = w + 8 * i;
        #pragma unroll
        for (int p = 0; p < PP; p++) {
            int bp = b * PP + p;
            float x = sx[ch * SXS + lane * 12 + p];
            float x2 = x * x;
            float ep = expf(x), en = expf(-x);
            size_t base = (((size_t)bp * 256 + ch) * NN + j0) + lane;
            const size_t G = (size_t)32 * NN;
            fh[base + 0 * G] = __float2half(x);
            fh[base + 1 * G] = __float2half(x2);
            fh[base + 2 * G] = __float2half(x2 * x);
            fh[base + 3 * G] = __float2half(x2 * x2);
            fh[base + 4 * G] = __float2half(x * ep);
            fh[base + 5 * G] = __float2half(ep);
            fh[base + 6 * G] = __float2half(x * en);
            fh[base + 7 * G] = __float2half(en);
        }
    }
}

// ---------------------------------------------------------------------------
__global__ __launch_bounds__(THREADS, 1)
void pna_kernel(const __grid_constant__ CUtensorMap a_map,
                const __grid_constant__ CUtensorMap f_map,
                const float* __restrict__ Theta, const float* __restrict__ Bias,
                float* __restrict__ out) {
    extern __shared__ uint32_t smu[];
    const uint32_t sbase = smem_u32(smu);
    const uint32_t mbar0 = sbase + MBAR_OFF;

    const int tid = threadIdx.x, lane = tid & 31, wid = tid >> 5;
    const int lq = lane >> 2, lr = lane & 3;
    const int wm = wid >> 2, wn = wid & 3;
    const int bp = blockIdx.y, i0 = blockIdx.x * TM;
    const int b = bp / PP, p = bp % PP;

    if (tid == 0) {
        #pragma unroll
        for (int i = 0; i < NBUF; i++) MBAR_INIT(mbar0 + 8 * i, 1);
    }
    __syncthreads();

    #define ISSUE(s) do {                                                     \
        int _bf = (s) & 3;                                                    \
        uint32_t _mb = mbar0 + 8 * _bf;                                       \
        uint32_t _sb = sbase + _bf * SB_BYTES;                                \
        MBAR_EXPECT_TX(_mb, SB_BYTES);                                        \
        TMA_LOAD_2D(_sb, &a_map, (s) * KT, i0, _mb);                          \
        TMA_LOAD_2D(_sb + A_TILE_B, &f_map, (s) * KT, bp * 256, _mb);         \
    } while (0)

    const int rowA = wm * 32 + (lane & 7) + ((lane >> 3) & 1) * 8;
    const uint32_t xorA = (uint32_t)((rowA & 7) << 4);
    const uint32_t colA = (uint32_t)(((lane >> 4) & 1) * 16);
    const uint32_t aoffb = (uint32_t)(rowA * 128);
    const int rowB = wn * 64 + (lane & 7) + ((lane >> 4) & 1) * 8;
    const uint32_t xorB = (uint32_t)((rowB & 7) << 4);
    const uint32_t colB = (uint32_t)(((lane >> 3) & 1) * 16);
    const uint32_t boffb = (uint32_t)(A_TILE_B + rowB * 128);

    float acc[2][8][4];
    #pragma unroll
    for (int mt = 0; mt < 2; mt++)
        #pragma unroll
        for (int nt = 0; nt < 8; nt++)
            #pragma unroll
            for (int j = 0; j < 4; j++) acc[mt][nt][j] = 0.f;

    if (tid == 0) { ISSUE(0); ISSUE(1); }

    const int NST = NN / KT;   // 32
    for (int s = 0; s < NST; s++) {
        // barrier only every 2 stages: warps may drift 1 stage apart,
        // ring depth 4 keeps refills safe (refill targets stages s-2/s-1 bufs)
        if ((s & 1) == 0) {
            __syncthreads();                  // all warps done through stage s-1
            if (tid == 0) {
                if (s + 2 < NST) ISSUE(s + 2);
                if (s + 3 < NST) ISSUE(s + 3);
            }
        }
        MBAR_WAIT(mbar0 + 8 * (s & 3), (s >> 2) & 1);

        const uint32_t stg = sbase + (uint32_t)((s & 3) * SB_BYTES);
        #pragma unroll
        for (int kb = 0; kb < 4; kb++) {
            const uint32_t ac = ((uint32_t)(kb * 32) + colA) ^ xorA;
            const uint32_t bc = ((uint32_t)(kb * 32) + colB) ^ xorB;
            uint32_t af[2][4], bf[4][4];
            #pragma unroll
            for (int mt = 0; mt < 2; mt++)
                ldsm_x4(af[mt], stg + aoffb + mt * 2048 + ac);
            #pragma unroll
            for (int ntp = 0; ntp < 4; ntp++)
                ldsm_x4(bf[ntp], stg + boffb + ntp * 2048 + bc);
            #pragma unroll
            for (int mt = 0; mt < 2; mt++)
                #pragma unroll
                for (int nt = 0; nt < 8; nt++)
                    mma_f16(acc[mt][nt], af[mt], bf[nt >> 1][(nt & 1) * 2],
                            bf[nt >> 1][(nt & 1) * 2 + 1]);
        }
    }
    #undef ISSUE
    __syncthreads();   // all MMAs done before epilogue reuses the ring

    // ---- spill accumulators to ACC[128][264] f32 ----
    float* ACCf = reinterpret_cast<float*>(smu);
    #pragma unroll
    for (int mt = 0; mt < 2; mt++) {
        int r = wm * 32 + mt * 16 + lq;
        #pragma unroll
        for (int nt = 0; nt < 8; nt++) {
            int c = wn * 64 + nt * 8 + lr * 2;
            float* a = acc[mt][nt];
            ACCf[r * ACCS + c]           = a[0];
            ACCf[r * ACCS + c + 1]       = a[1];
            ACCf[(r + 8) * ACCS + c]     = a[2];
            ACCf[(r + 8) * ACCS + c + 1] = a[3];
        }
    }
    __syncthreads();

    // ---- phase A: aggregators -> feats fp16 ----
    __half* Fbh = reinterpret_cast<__half*>(smu + FEAT_OFF);
    const float* xp = g_xp + (size_t)bp * NN * CC;
    for (int e = tid; e < TM * 32; e += THREADS) {
        int il = e >> 5, ch = e & 31;
        const float* row = &ACCf[il * ACCS];
        float S1  = row[ch],       S2  = row[32 + ch];
        float S3  = row[64 + ch],  S4  = row[96 + ch];
        float SXP = row[128 + ch], SEP = row[160 + ch];
        float SXN = row[192 + ch], SEN = row[224 + ch];

        int i = i0 + il;
        float x    = xp[(size_t)i * CC + ch];
        float dg   = g_deg[i];
        float dinv = 1.f / fmaxf(dg, EPSV);
        float m1 = S1 * dinv, m2 = S2 * dinv, m3 = S3 * dinv, m4 = S4 * dinv;
        float smax = SXP / (SEP + EPSV);
        float smin = SXN / (SEN + EPSV);
        float var  = fmaxf(m2 - m1 * m1, 0.f);
        float stdv = sqrtf(var + EPSV);
        float x2 = x * x, x3 = x2 * x, x4 = x2 * x2;
        float dist = x2 - 2.f * x * m1 + m2;
        float ed2  = x4 - 4.f * x3 * m1 + 6.f * x2 * m2 - 4.f * x * m3 + m4;
        float dstd = sqrtf(fmaxf(ed2 - dist * dist, 0.f) + EPSV);

        __half* fr = Fbh + (size_t)il * (2 * FBS);
        fr[0 * 32 + ch] = __float2half(smin);
        fr[1 * 32 + ch] = __float2half(smax);
        fr[2 * 32 + ch] = __float2half(m1);
        fr[3 * 32 + ch] = __float2half(stdv);
        fr[4 * 32 + ch] = __float2half(var);
        fr[5 * 32 + ch] = __float2half(dist);
        fr[6 * 32 + ch] = __float2half(dstd);
    }
    __syncthreads();

    // ---- stage ThetaB fp16 into dead ACC region ----
    for (int idx = tid; idx < 96 * 112; idx += THREADS) {
        int p2 = idx / 96, n = idx % 96;
        int q = n >> 5, o = n & 31;
        float f0 = Theta[(size_t)(224 * q + 2 * p2) * OUTC + o];
        float f1 = Theta[(size_t)(224 * q + 2 * p2 + 1) * OUTC + o];
        smu[THB_OFF + n * FBS + p2] = pack_h2(f0, f1);
    }
    __syncthreads();

    // ---- GEMM2 (fp16): D[128][96] = feats[128x224] @ ThetaB^T ----
    {
        const uint32_t* Fb = smu + FEAT_OFF;
        const uint32_t* Tb = smu + THB_OFF;
        const int wm2 = wid >> 1, wn2 = wid & 1;
        float a2[6][4];
        #pragma unroll
        for (int nt = 0; nt < 6; nt++)
            #pragma unroll
            for (int j = 0; j < 4; j++) a2[nt][j] = 0.f;

        #pragma unroll 2
        for (int kb = 0; kb < 14; kb++) {
            uint32_t af[4], bfv[6][2];
            int r = (wm2 * 16 + lq) * FBS + kb * 8 + lr;
            af[0] = Fb[r];
            af[1] = Fb[r + 8 * FBS];
            af[2] = Fb[r + 4];
            af[3] = Fb[r + 8 * FBS + 4];
            #pragma unroll
            for (int nt = 0; nt < 6; nt++) {
                int c = (wn2 * 48 + nt * 8 + lq) * FBS + kb * 8 + lr;
                bfv[nt][0] = Tb[c];
                bfv[nt][1] = Tb[c + 4];
            }
            #pragma unroll
            for (int nt = 0; nt < 6; nt++)
                mma_f16(a2[nt], af, bfv[nt][0], bfv[nt][1]);
        }
        __syncthreads();
        float* D = reinterpret_cast<float*>(smu + D_OFF);
        int r = wm2 * 16 + lq;
        #pragma unroll
        for (int nt = 0; nt < 6; nt++) {
            int c = wn2 * 48 + nt * 8 + 2 * lr;
            D[r * 100 + c]           = a2[nt][0];
            D[r * 100 + c + 1]       = a2[nt][1];
            D[(r + 8) * 100 + c]     = a2[nt][2];
            D[(r + 8) * 100 + c + 1] = a2[nt][3];
        }
        __syncthreads();

        int i = tid >> 2;
        int ob = (tid & 3) * 8;
        float dg = g_deg[i0 + i];
        float sv = logf(dg + 1.f) / g_delta;
        float iv = 1.f / fmaxf(sv, EPSV);
        #pragma unroll
        for (int k = 0; k < 8; k++) {
            int o = ob + k;
            float v = D[i * 100 + o] + sv * D[i * 100 + 32 + o] +
                      iv * D[i * 100 + 64 + o] + Bias[o];
            v = v > 0.f ? v : NEG_SLOPE * v;
            out[(((size_t)b * OUTC + o) * NN + (i0 + i)) * PP + p] = v;
        }
    }
}

// ---------------------------------------------------------------------------
typedef CUresult (*PFN_encodeTiled)(CUtensorMap*, CUtensorMapDataType, cuuint32_t,
                                    void*, const cuuint64_t*, const cuuint64_t*,
                                    const cuuint32_t*, const cuuint32_t*,
                                    CUtensorMapInterleave, CUtensorMapSwizzle,
                                    CUtensorMapL2promotion, CUtensorMapFloatOOBfill);

extern "C" void kernel_launch(void* const* d_in, const int* in_sizes, int n_in,
                              void* d_out, int out_size) {
    const float* X     = (const float*)d_in[0];
    const float* A     = (const float*)d_in[1];
    const float* Theta = (const float*)d_in[2];
    const float* Bias  = (const float*)d_in[3];
    float* out = (float*)d_out;

    void* fn = nullptr;
    cudaDriverEntryPointQueryResult qr;
#if CUDART_VERSION >= 12050
    cudaGetDriverEntryPointByVersion("cuTensorMapEncodeTiled", &fn, 12000,
                                     cudaEnableDefault, &qr);
#else
    cudaGetDriverEntryPoint("cuTensorMapEncodeTiled", &fn, cudaEnableDefault, &qr);
#endif
    PFN_encodeTiled encode = (PFN_encodeTiled)fn;

    void *dA = nullptr, *dF = nullptr;
    cudaGetSymbolAddress(&dA, g_ahf);
    cudaGetSymbolAddress(&dF, g_fhf);

    CUtensorMap a_map, f_map;
    {
        cuuint64_t dims[2]    = {NN, NN};
        cuuint64_t strides[1] = {(cuuint64_t)NN * 2};
        cuuint32_t box[2]     = {KT, 128};
        cuuint32_t es[2]      = {1, 1};
        encode(&a_map, CU_TENSOR_MAP_DATA_TYPE_FLOAT16, 2, dA, dims, strides, box, es,
               CU_TENSOR_MAP_INTERLEAVE_NONE, CU_TENSOR_MAP_SWIZZLE_128B,
               CU_TENSOR_MAP_L2_PROMOTION_L2_128B, CU_TENSOR_MAP_FLOAT_OOB_FILL_NONE);
    }
    {
        cuuint64_t dims[2]    = {NN, (cuuint64_t)BB * PP * 256};
        cuuint64_t strides[1] = {(cuuint64_t)NN * 2};
        cuuint32_t box[2]     = {KT, 256};
        cuuint32_t es[2]      = {1, 1};
        encode(&f_map, CU_TENSOR_MAP_DATA_TYPE_FLOAT16, 2, dF, dims, strides, box, es,
               CU_TENSOR_MAP_INTERLEAVE_NONE, CU_TENSOR_MAP_SWIZZLE_128B,
               CU_TENSOR_MAP_L2_PROMOTION_L2_128B, CU_TENSOR_MAP_FLOAT_OOB_FILL_NONE);
    }

    cudaFuncSetAttribute(pna_kernel, cudaFuncAttributeMaxDynamicSharedMemorySize,
                         SMEM_BYTES);
    cudaFuncSetAttribute(xf_kernel, cudaFuncAttributeMaxDynamicSharedMemorySize,
                         CC * SXS * 4);

    ahf_deg_kernel<<<NN / 8, 256>>>(A);
    delta_kernel<<<1, 1024>>>();
    xf_kernel<<<dim3(NN / 32, BB), 256, CC * SXS * 4>>>(X);

    dim3 grid(NN / TM, BB * PP);
    pna_kernel<<<grid, THREADS, SMEM_BYTES>>>(a_map, f_map, Theta, Bias, out);
}

// round 15
// speedup vs baseline: 1.9974x; 1.0359x over previous
#include <cuda_runtime.h>
#include <cuda_fp16.h>
#include <cuda.h>
#include <math.h>
#include <stdint.h>

#define BB   4
#define CC   32
#define NN   2048
#define PP   12
#define OUTC 32
#define TM   128
#define KT   64
#define THREADS 512
#define EPSV 1e-5f
#define NEG_SLOPE 0.01f

// ---- pna smem layout ----
#define A_TILE_B  16384
#define SB_BYTES  49152
#define NBUF      4
#define MBAR_OFF  196608        // full[4] @ +0, done[4] @ +32
#define SMEM_BYTES 196736
#define ACCS     264
#define FEAT_OFF 33792
#define FBS      116
#define THB_OFF  0
#define D_OFF    12800

__device__ __align__(1024) __half g_ahf[(size_t)NN * NN];
__device__ __align__(1024) __half g_fhf[(size_t)BB * PP * 256 * NN];
__device__ float g_xp[(size_t)BB * PP * NN * CC];
__device__ float g_deg[NN];
__device__ float g_delta;

// ---------------------------------------------------------------------------
__device__ __forceinline__ uint32_t smem_u32(const void* p) {
    uint32_t a;
    asm("{ .reg .u64 t; cvta.to.shared.u64 t, %1; cvt.u32.u64 %0, t; }" : "=r"(a) : "l"(p));
    return a;
}
#define MBAR_INIT(a, n) \
    asm volatile("mbarrier.init.shared.b64 [%0], %1;" :: "r"(a), "r"(n) : "memory")
#define MBAR_EXPECT_TX(a, bytes) \
    asm volatile("mbarrier.arrive.expect_tx.shared.b64 _, [%0], %1;" :: "r"(a), "r"(bytes) : "memory")
#define MBAR_ARRIVE(a) \
    asm volatile("mbarrier.arrive.shared.b64 _, [%0];" :: "r"(a) : "memory")
#define MBAR_WAIT(a, ph) do { \
    asm volatile("{\n\t.reg .pred P1;\n\tWL_%=:\n\t" \
        "mbarrier.try_wait.parity.acquire.cta.shared::cta.b64 P1, [%0], %1, 0x989680;\n\t" \
        "@P1 bra.uni WD_%=;\n\tbra.uni WL_%=;\n\tWD_%=:\n\t}" \
        :: "r"(a), "r"(ph) : "memory"); } while (0)
#define TMA_LOAD_2D(saddr, map, cx, cy, mbar) \
    asm volatile("cp.async.bulk.tensor.2d.shared::cta.global.tile.mbarrier::complete_tx::bytes " \
        "[%0], [%1, {%2, %3}], [%4];" \
        :: "r"((uint32_t)(saddr)), "l"(map), "r"((int)(cx)), "r"((int)(cy)), \
           "r"((uint32_t)(mbar)) : "memory")

__device__ __forceinline__ void ldsm_x4(uint32_t r[4], uint32_t addr) {
    asm volatile("ldmatrix.sync.aligned.m8n8.x4.shared.b16 {%0,%1,%2,%3}, [%4];"
        : "=r"(r[0]), "=r"(r[1]), "=r"(r[2]), "=r"(r[3]) : "r"(addr));
}
__device__ __forceinline__ void mma_f16(float c[4], const uint32_t a[4],
                                        const uint32_t b0, const uint32_t b1) {
    asm volatile(
        "mma.sync.aligned.m16n8k16.row.col.f32.f16.f16.f32 "
        "{%0,%1,%2,%3}, {%4,%5,%6,%7}, {%8,%9}, {%0,%1,%2,%3};"
        : "+f"(c[0]), "+f"(c[1]), "+f"(c[2]), "+f"(c[3])
        : "r"(a[0]), "r"(a[1]), "r"(a[2]), "r"(a[3]), "r"(b0), "r"(b1));
}
__device__ __forceinline__ uint32_t pack_h2(float lo, float hi) {
    __half2 h = __floats2half2_rn(lo, hi);
    return *reinterpret_cast<uint32_t*>(&h);
}

// ---------------------------------------------------------------------------
// fused: A -> fp16 conversion + row-degree (warp per row)
__global__ void ahf_deg_kernel(const float* __restrict__ A) {
    int row  = blockIdx.x * 8 + (threadIdx.x >> 5);
    int lane = threadIdx.x & 31;
    const float4* src = reinterpret_cast<const float4*>(A + (size_t)row * NN);
    uint32_t* dst = reinterpret_cast<uint32_t*>(g_ahf) + (size_t)row * (NN / 2);
    float s = 0.f;
    #pragma unroll
    for (int k = 0; k < 16; k++) {
        float4 v = src[lane + 32 * k];
        s += (v.x + v.y) + (v.z + v.w);
        dst[2 * (lane + 32 * k)]     = pack_h2(v.x, v.y);
        dst[2 * (lane + 32 * k) + 1] = pack_h2(v.z, v.w);
    }
    #pragma unroll
    for (int o = 16; o; o >>= 1) s += __shfl_xor_sync(0xffffffffu, s, o);
    if (lane == 0) g_deg[row] = s;
}

__global__ void delta_kernel() {
    __shared__ float red[32];
    int tid = threadIdx.x;
    float s = 0.f;
    for (int i = tid; i < NN; i += blockDim.x) s += logf(g_deg[i] + 1.f);
    #pragma unroll
    for (int o = 16; o; o >>= 1) s += __shfl_xor_sync(0xffffffffu, s, o);
    if ((tid & 31) == 0) red[tid >> 5] = s;
    __syncthreads();
    if (tid < 32) {
        float v = (tid < (int)(blockDim.x >> 5)) ? red[tid] : 0.f;
        #pragma unroll
        for (int o = 16; o; o >>= 1) v += __shfl_xor_sync(0xffffffffu, v, o);
        if (tid == 0) g_delta = v / (float)NN;
    }
}

// coalesced: transpose X -> g_xp AND build fp16 feature planes g_fhf
#define SXS 387
__global__ void xf_kernel(const float* __restrict__ X) {
    extern __shared__ float sx[];
    const int b  = blockIdx.y;
    const int j0 = blockIdx.x * 32;
    const int t  = threadIdx.x;       // 256
    const int lane = t & 31, w = t >> 5;

    #pragma unroll
    for (int i = 0; i < 48; i++) {
        int e = t + 256 * i;
        int ch = e / 384, rem = e - ch * 384;
        sx[ch * SXS + rem] = X[((size_t)(b * CC + ch) * NN + j0) * PP + rem];
    }
    __syncthreads();

    #pragma unroll
    for (int p = 0; p < PP; p++) {
        int bp = b * PP + p;
        float* xpd = g_xp + ((size_t)bp * NN + j0) * CC;
        #pragma unroll
        for (int i = 0; i < 4; i++) {
            int e = t + 256 * i;
            int j = e >> 5, ch = e & 31;
            xpd[j * CC + ch] = sx[ch * SXS + j * 12 + p];
        }
    }

    __half* fh = reinterpret_cast<__half*>(g_fhf);
    #pragma unroll
    for (int i = 0; i < 4; i++) {
        int ch = w + 8 * i;
        #pragma unroll
        for (int p = 0; p < PP; p++) {
            int bp = b * PP + p;
            float x = sx[ch * SXS + lane * 12 + p];
            float x2 = x * x;
            float ep = expf(x), en = expf(-x);
            size_t base = (((size_t)bp * 256 + ch) * NN + j0) + lane;
            const size_t G = (size_t)32 * NN;
            fh[base + 0 * G] = __float2half(x);
            fh[base + 1 * G] = __float2half(x2);
            fh[base + 2 * G] = __float2half(x2 * x);
            fh[base + 3 * G] = __float2half(x2 * x2);
            fh[base + 4 * G] = __float2half(x * ep);
            fh[base + 5 * G] = __float2half(ep);
            fh[base + 6 * G] = __float2half(x * en);
            fh[base + 7 * G] = __float2half(en);
        }
    }
}

// ---------------------------------------------------------------------------
__global__ __launch_bounds__(THREADS, 1)
void pna_kernel(const __grid_constant__ CUtensorMap a_map,
                const __grid_constant__ CUtensorMap f_map,
                const float* __restrict__ Theta, const float* __restrict__ Bias,
                float* __restrict__ out) {
    extern __shared__ uint32_t smu[];
    const uint32_t sbase = smem_u32(smu);
    const uint32_t mb_full = sbase + MBAR_OFF;
    const uint32_t mb_done = sbase + MBAR_OFF + 32;

    const int tid = threadIdx.x, lane = tid & 31, wid = tid >> 5;
    const int lq = lane >> 2, lr = lane & 3;
    const int wm = wid >> 2, wn = wid & 3;
    const int bp = blockIdx.y, i0 = blockIdx.x * TM;
    const int b = bp / PP, p = bp % PP;

    if (tid == 0) {
        #pragma unroll
        for (int i = 0; i < NBUF; i++) {
            MBAR_INIT(mb_full + 8 * i, 1);
            MBAR_INIT(mb_done + 8 * i, 16);   // one arrive per warp
        }
    }
    __syncthreads();

    #define ISSUE(s) do {                                                     \
        int _bf = (s) & 3;                                                    \
        uint32_t _mb = mb_full + 8 * _bf;                                     \
        uint32_t _sb = sbase + _bf * SB_BYTES;                                \
        MBAR_EXPECT_TX(_mb, SB_BYTES);                                        \
        TMA_LOAD_2D(_sb, &a_map, (s) * KT, i0, _mb);                          \
        TMA_LOAD_2D(_sb + A_TILE_B, &f_map, (s) * KT, bp * 256, _mb);         \
    } while (0)

    const int rowA = wm * 32 + (lane & 7) + ((lane >> 3) & 1) * 8;
    const uint32_t xorA = (uint32_t)((rowA & 7) << 4);
    const uint32_t colA = (uint32_t)(((lane >> 4) & 1) * 16);
    const uint32_t aoffb = (uint32_t)(rowA * 128);
    const int rowB = wn * 64 + (lane & 7) + ((lane >> 4) & 1) * 8;
    const uint32_t xorB = (uint32_t)((rowB & 7) << 4);
    const uint32_t colB = (uint32_t)(((lane >> 3) & 1) * 16);
    const uint32_t boffb = (uint32_t)(A_TILE_B + rowB * 128);

    float acc[2][8][4];
    #pragma unroll
    for (int mt = 0; mt < 2; mt++)
        #pragma unroll
        for (int nt = 0; nt < 8; nt++)
            #pragma unroll
            for (int j = 0; j < 4; j++) acc[mt][nt][j] = 0.f;

    if (tid == 0) { ISSUE(0); ISSUE(1); ISSUE(2); }

    const int NST = NN / KT;   // 32
    for (int s = 0; s < NST; s++) {
        // producer: refill buffer (s+3)&3 once all warps released it (stage s-1)
        if (tid == 0 && s + 3 < NST) {
            if (s >= 1) MBAR_WAIT(mb_done + 8 * ((s + 3) & 3), ((s - 1) >> 2) & 1);
            ISSUE(s + 3);
        }
        // consumer: wait data for stage s
        MBAR_WAIT(mb_full + 8 * (s & 3), (s >> 2) & 1);

        const uint32_t stg = sbase + (uint32_t)((s & 3) * SB_BYTES);
        #pragma unroll
        for (int kb = 0; kb < 4; kb++) {
            const uint32_t ac = ((uint32_t)(kb * 32) + colA) ^ xorA;
            const uint32_t bc = ((uint32_t)(kb * 32) + colB) ^ xorB;
            uint32_t af[2][4], bf[4][4];
            #pragma unroll
            for (int mt = 0; mt < 2; mt++)
                ldsm_x4(af[mt], stg + aoffb + mt * 2048 + ac);
            #pragma unroll
            for (int ntp = 0; ntp < 4; ntp++)
                ldsm_x4(bf[ntp], stg + boffb + ntp * 2048 + bc);
            #pragma unroll
            for (int mt = 0; mt < 2; mt++)
                #pragma unroll
                for (int nt = 0; nt < 8; nt++)
                    mma_f16(acc[mt][nt], af[mt], bf[nt >> 1][(nt & 1) * 2],
                            bf[nt >> 1][(nt & 1) * 2 + 1]);
        }
        // this warp is done reading buffer s&3
        if (lane == 0) MBAR_ARRIVE(mb_done + 8 * (s & 3));
    }
    #undef ISSUE
    __syncthreads();   // all warps past mainloop before epilogue reuses the ring

    // ---- spill accumulators to ACC[128][264] f32 ----
    float* ACCf = reinterpret_cast<float*>(smu);
    #pragma unroll
    for (int mt = 0; mt < 2; mt++) {
        int r = wm * 32 + mt * 16 + lq;
        #pragma unroll
        for (int nt = 0; nt < 8; nt++) {
            int c = wn * 64 + nt * 8 + lr * 2;
            float* a = acc[mt][nt];
            ACCf[r * ACCS + c]           = a[0];
            ACCf[r * ACCS + c + 1]       = a[1];
            ACCf[(r + 8) * ACCS + c]     = a[2];
            ACCf[(r + 8) * ACCS + c + 1] = a[3];
        }
    }
    __syncthreads();

    // ---- phase A: aggregators -> feats fp16 ----
    __half* Fbh = reinterpret_cast<__half*>(smu + FEAT_OFF);
    const float* xp = g_xp + (size_t)bp * NN * CC;
    for (int e = tid; e < TM * 32; e += THREADS) {
        int il = e >> 5, ch = e & 31;
        const float* row = &ACCf[il * ACCS];
        float S1  = row[ch],       S2  = row[32 + ch];
        float S3  = row[64 + ch],  S4  = row[96 + ch];
        float SXP = row[128 + ch], SEP = row[160 + ch];
        float SXN = row[192 + ch], SEN = row[224 + ch];

        int i = i0 + il;
        float x    = xp[(size_t)i * CC + ch];
        float dg   = g_deg[i];
        float dinv = 1.f / fmaxf(dg, EPSV);
        float m1 = S1 * dinv, m2 = S2 * dinv, m3 = S3 * dinv, m4 = S4 * dinv;
        float smax = SXP / (SEP + EPSV);
        float smin = SXN / (SEN + EPSV);
        float var  = fmaxf(m2 - m1 * m1, 0.f);
        float stdv = sqrtf(var + EPSV);
        float x2 = x * x, x3 = x2 * x, x4 = x2 * x2;
        float dist = x2 - 2.f * x * m1 + m2;
        float ed2  = x4 - 4.f * x3 * m1 + 6.f * x2 * m2 - 4.f * x * m3 + m4;
        float dstd = sqrtf(fmaxf(ed2 - dist * dist, 0.f) + EPSV);

        __half* fr = Fbh + (size_t)il * (2 * FBS);
        fr[0 * 32 + ch] = __float2half(smin);
        fr[1 * 32 + ch] = __float2half(smax);
        fr[2 * 32 + ch] = __float2half(m1);
        fr[3 * 32 + ch] = __float2half(stdv);
        fr[4 * 32 + ch] = __float2half(var);
        fr[5 * 32 + ch] = __float2half(dist);
        fr[6 * 32 + ch] = __float2half(dstd);
    }
    __syncthreads();

    // ---- stage ThetaB fp16 into dead ACC region ----
    for (int idx = tid; idx < 96 * 112; idx += THREADS) {
        int p2 = idx / 96, n = idx % 96;
        int q = n >> 5, o = n & 31;
        float f0 = Theta[(size_t)(224 * q + 2 * p2) * OUTC + o];
        float f1 = Theta[(size_t)(224 * q + 2 * p2 + 1) * OUTC + o];
        smu[THB_OFF + n * FBS + p2] = pack_h2(f0, f1);
    }
    __syncthreads();

    // ---- GEMM2 (fp16): D[128][96] = feats[128x224] @ ThetaB^T ----
    {
        const uint32_t* Fb = smu + FEAT_OFF;
        const uint32_t* Tb = smu + THB_OFF;
        const int wm2 = wid >> 1, wn2 = wid & 1;
        float a2[6][4];
        #pragma unroll
        for (int nt = 0; nt < 6; nt++)
            #pragma unroll
            for (int j = 0; j < 4; j++) a2[nt][j] = 0.f;

        #pragma unroll 2
        for (int kb = 0; kb < 14; kb++) {
            uint32_t af[4], bfv[6][2];
            int r = (wm2 * 16 + lq) * FBS + kb * 8 + lr;
            af[0] = Fb[r];
            af[1] = Fb[r + 8 * FBS];
            af[2] = Fb[r + 4];
            af[3] = Fb[r + 8 * FBS + 4];
            #pragma unroll
            for (int nt = 0; nt < 6; nt++) {
                int c = (wn2 * 48 + nt * 8 + lq) * FBS + kb * 8 + lr;
                bfv[nt][0] = Tb[c];
                bfv[nt][1] = Tb[c + 4];
            }
            #pragma unroll
            for (int nt = 0; nt < 6; nt++)
                mma_f16(a2[nt], af, bfv[nt][0], bfv[nt][1]);
        }
        __syncthreads();
        float* D = reinterpret_cast<float*>(smu + D_OFF);
        int r = wm2 * 16 + lq;
        #pragma unroll
        for (int nt = 0; nt < 6; nt++) {
            int c = wn2 * 48 + nt * 8 + 2 * lr;
            D[r * 100 + c]           = a2[nt][0];
            D[r * 100 + c + 1]       = a2[nt][1];
            D[(r + 8) * 100 + c]     = a2[nt][2];
            D[(r + 8) * 100 + c + 1] = a2[nt][3];
        }
        __syncthreads();

        int i = tid >> 2;
        int ob = (tid & 3) * 8;
        float dg = g_deg[i0 + i];
        float sv = logf(dg + 1.f) / g_delta;
        float iv = 1.f / fmaxf(sv, EPSV);
        #pragma unroll
        for (int k = 0; k < 8; k++) {
            int o = ob + k;
            float v = D[i * 100 + o] + sv * D[i * 100 + 32 + o] +
                      iv * D[i * 100 + 64 + o] + Bias[o];
            v = v > 0.f ? v : NEG_SLOPE * v;
            out[(((size_t)b * OUTC + o) * NN + (i0 + i)) * PP + p] = v;
        }
    }
}

// ---------------------------------------------------------------------------
typedef CUresult (*PFN_encodeTiled)(CUtensorMap*, CUtensorMapDataType, cuuint32_t,
                                    void*, const cuuint64_t*, const cuuint64_t*,
                                    const cuuint32_t*, const cuuint32_t*,
                                    CUtensorMapInterleave, CUtensorMapSwizzle,
                                    CUtensorMapL2promotion, CUtensorMapFloatOOBfill);

extern "C" void kernel_launch(void* const* d_in, const int* in_sizes, int n_in,
                              void* d_out, int out_size) {
    const float* X     = (const float*)d_in[0];
    const float* A     = (const float*)d_in[1];
    const float* Theta = (const float*)d_in[2];
    const float* Bias  = (const float*)d_in[3];
    float* out = (float*)d_out;

    void* fn = nullptr;
    cudaDriverEntryPointQueryResult qr;
#if CUDART_VERSION >= 12050
    cudaGetDriverEntryPointByVersion("cuTensorMapEncodeTiled", &fn, 12000,
                                     cudaEnableDefault, &qr);
#else
    cudaGetDriverEntryPoint("cuTensorMapEncodeTiled", &fn, cudaEnableDefault, &qr);
#endif
    PFN_encodeTiled encode = (PFN_encodeTiled)fn;

    void *dA = nullptr, *dF = nullptr;
    cudaGetSymbolAddress(&dA, g_ahf);
    cudaGetSymbolAddress(&dF, g_fhf);

    CUtensorMap a_map, f_map;
    {
        cuuint64_t dims[2]    = {NN, NN};
        cuuint64_t strides[1] = {(cuuint64_t)NN * 2};
        cuuint32_t box[2]     = {KT, 128};
        cuuint32_t es[2]      = {1, 1};
        encode(&a_map, CU_TENSOR_MAP_DATA_TYPE_FLOAT16, 2, dA, dims, strides, box, es,
               CU_TENSOR_MAP_INTERLEAVE_NONE, CU_TENSOR_MAP_SWIZZLE_128B,
               CU_TENSOR_MAP_L2_PROMOTION_L2_128B, CU_TENSOR_MAP_FLOAT_OOB_FILL_NONE);
    }
    {
        cuuint64_t dims[2]    = {NN, (cuuint64_t)BB * PP * 256};
        cuuint64_t strides[1] = {(cuuint64_t)NN * 2};
        cuuint32_t box[2]     = {KT, 256};
        cuuint32_t es[2]      = {1, 1};
        encode(&f_map, CU_TENSOR_MAP_DATA_TYPE_FLOAT16, 2, dF, dims, strides, box, es,
               CU_TENSOR_MAP_INTERLEAVE_NONE, CU_TENSOR_MAP_SWIZZLE_128B,
               CU_TENSOR_MAP_L2_PROMOTION_L2_128B, CU_TENSOR_MAP_FLOAT_OOB_FILL_NONE);
    }

    cudaFuncSetAttribute(pna_kernel, cudaFuncAttributeMaxDynamicSharedMemorySize,
                         SMEM_BYTES);
    cudaFuncSetAttribute(xf_kernel, cudaFuncAttributeMaxDynamicSharedMemorySize,
                         CC * SXS * 4);

    ahf_deg_kernel<<<NN / 8, 256>>>(A);
    delta_kernel<<<1, 1024>>>();
    xf_kernel<<<dim3(NN / 32, BB), 256, CC * SXS * 4>>>(X);

    dim3 grid(NN / TM, BB * PP);
    pna_kernel<<<grid, THREADS, SMEM_BYTES>>>(a_map, f_map, Theta, Bias, out);
}

// round 16
// speedup vs baseline: 2.0255x; 1.0140x over previous
#include <cuda_runtime.h>
#include <cuda_fp16.h>
#include <cuda.h>
#include <math.h>
#include <stdint.h>

#define BB   4
#define CC   32
#define NN   2048
#define PP   12
#define OUTC 32
#define TM   128
#define KT   128
#define THREADS 512
#define EPSV 1e-5f
#define NEG_SLOPE 0.01f

// ---- pna smem layout ----
// stage: A0[128][128B]@0, A1@16384, F0[256][128B]@32768, F1@65536
#define SB_BYTES  98304
#define NBUF      2
#define MBAR_OFF  196608        // full[2] @ +0, done[2] @ +32
#define SMEM_BYTES 196736
#define ACCS     264
#define FEAT_OFF 33792
#define FBS      116
#define THB_OFF  0
#define D_OFF    12800

__device__ __align__(1024) __half g_ahf[(size_t)NN * NN];
__device__ __align__(1024) __half g_fhf[(size_t)BB * PP * 256 * NN];
__device__ float g_xp[(size_t)BB * PP * NN * CC];
__device__ float g_deg[NN];
__device__ float g_delta;

// ---------------------------------------------------------------------------
__device__ __forceinline__ uint32_t smem_u32(const void* p) {
    uint32_t a;
    asm("{ .reg .u64 t; cvta.to.shared.u64 t, %1; cvt.u32.u64 %0, t; }" : "=r"(a) : "l"(p));
    return a;
}
#define MBAR_INIT(a, n) \
    asm volatile("mbarrier.init.shared.b64 [%0], %1;" :: "r"(a), "r"(n) : "memory")
#define MBAR_EXPECT_TX(a, bytes) \
    asm volatile("mbarrier.arrive.expect_tx.shared.b64 _, [%0], %1;" :: "r"(a), "r"(bytes) : "memory")
#define MBAR_ARRIVE(a) \
    asm volatile("mbarrier.arrive.shared.b64 _, [%0];" :: "r"(a) : "memory")
#define MBAR_WAIT(a, ph) do { \
    asm volatile("{\n\t.reg .pred P1;\n\tWL_%=:\n\t" \
        "mbarrier.try_wait.parity.acquire.cta.shared::cta.b64 P1, [%0], %1, 0x989680;\n\t" \
        "@P1 bra.uni WD_%=;\n\tbra.uni WL_%=;\n\tWD_%=:\n\t}" \
        :: "r"(a), "r"(ph) : "memory"); } while (0)
#define TMA_LOAD_2D(saddr, map, cx, cy, mbar) \
    asm volatile("cp.async.bulk.tensor.2d.shared::cta.global.tile.mbarrier::complete_tx::bytes " \
        "[%0], [%1, {%2, %3}], [%4];" \
        :: "r"((uint32_t)(saddr)), "l"(map), "r"((int)(cx)), "r"((int)(cy)), \
           "r"((uint32_t)(mbar)) : "memory")

__device__ __forceinline__ void ldsm_x4(uint32_t r[4], uint32_t addr) {
    asm volatile("ldmatrix.sync.aligned.m8n8.x4.shared.b16 {%0,%1,%2,%3}, [%4];"
        : "=r"(r[0]), "=r"(r[1]), "=r"(r[2]), "=r"(r[3]) : "r"(addr));
}
__device__ __forceinline__ void mma_f16(float c[4], const uint32_t a[4],
                                        const uint32_t b0, const uint32_t b1) {
    asm volatile(
        "mma.sync.aligned.m16n8k16.row.col.f32.f16.f16.f32 "
        "{%0,%1,%2,%3}, {%4,%5,%6,%7}, {%8,%9}, {%0,%1,%2,%3};"
        : "+f"(c[0]), "+f"(c[1]), "+f"(c[2]), "+f"(c[3])
        : "r"(a[0]), "r"(a[1]), "r"(a[2]), "r"(a[3]), "r"(b0), "r"(b1));
}
__device__ __forceinline__ uint32_t pack_h2(float lo, float hi) {
    __half2 h = __floats2half2_rn(lo, hi);
    return *reinterpret_cast<uint32_t*>(&h);
}

// ---------------------------------------------------------------------------
// fused prep: y<BB -> X transpose + feature planes ; y==BB -> A fp16 + degree
#define SXS 387
__global__ void prep_kernel(const float* __restrict__ X, const float* __restrict__ A) {
    const int t = threadIdx.x;   // 256
    const int lane = t & 31, w = t >> 5;

    if (blockIdx.y == BB) {
        // ---- A role: 32 rows per block, warp per row, 4 passes ----
        #pragma unroll
        for (int it = 0; it < 4; it++) {
            int row = blockIdx.x * 32 + it * 8 + w;
            const float4* src = reinterpret_cast<const float4*>(A + (size_t)row * NN);
            uint32_t* dst = reinterpret_cast<uint32_t*>(g_ahf) + (size_t)row * (NN / 2);
            float s = 0.f;
            #pragma unroll
            for (int k = 0; k < 16; k++) {
                float4 v = src[lane + 32 * k];
                s += (v.x + v.y) + (v.z + v.w);
                dst[2 * (lane + 32 * k)]     = pack_h2(v.x, v.y);
                dst[2 * (lane + 32 * k) + 1] = pack_h2(v.z, v.w);
            }
            #pragma unroll
            for (int o = 16; o; o >>= 1) s += __shfl_xor_sync(0xffffffffu, s, o);
            if (lane == 0) g_deg[row] = s;
        }
        return;
    }

    // ---- xf role ----
    extern __shared__ float sx[];
    const int b  = blockIdx.y;
    const int j0 = blockIdx.x * 32;

    #pragma unroll
    for (int i = 0; i < 48; i++) {
        int e = t + 256 * i;
        int ch = e / 384, rem = e - ch * 384;
        sx[ch * SXS + rem] = X[((size_t)(b * CC + ch) * NN + j0) * PP + rem];
    }
    __syncthreads();

    #pragma unroll
    for (int p = 0; p < PP; p++) {
        int bp = b * PP + p;
        float* xpd = g_xp + ((size_t)bp * NN + j0) * CC;
        #pragma unroll
        for (int i = 0; i < 4; i++) {
            int e = t + 256 * i;
            int j = e >> 5, ch = e & 31;
            xpd[j * CC + ch] = sx[ch * SXS + j * 12 + p];
        }
    }

    __half* fh = reinterpret_cast<__half*>(g_fhf);
    #pragma unroll
    for (int i = 0; i < 4; i++) {
        int ch = w + 8 * i;
        #pragma unroll
        for (int p = 0; p < PP; p++) {
            int bp = b * PP + p;
            float x = sx[ch * SXS + lane * 12 + p];
            float x2 = x * x;
            float ep = expf(x), en = expf(-x);
            size_t base = (((size_t)bp * 256 + ch) * NN + j0) + lane;
            const size_t G = (size_t)32 * NN;
            fh[base + 0 * G] = __float2half(x);
            fh[base + 1 * G] = __float2half(x2);
            fh[base + 2 * G] = __float2half(x2 * x);
            fh[base + 3 * G] = __float2half(x2 * x2);
            fh[base + 4 * G] = __float2half(x * ep);
            fh[base + 5 * G] = __float2half(ep);
            fh[base + 6 * G] = __float2half(x * en);
            fh[base + 7 * G] = __float2half(en);
        }
    }
}

__global__ void delta_kernel() {
    __shared__ float red[32];
    int tid = threadIdx.x;
    float s = 0.f;
    for (int i = tid; i < NN; i += blockDim.x) s += logf(g_deg[i] + 1.f);
    #pragma unroll
    for (int o = 16; o; o >>= 1) s += __shfl_xor_sync(0xffffffffu, s, o);
    if ((tid & 31) == 0) red[tid >> 5] = s;
    __syncthreads();
    if (tid < 32) {
        float v = (tid < (int)(blockDim.x >> 5)) ? red[tid] : 0.f;
        #pragma unroll
        for (int o = 16; o; o >>= 1) v += __shfl_xor_sync(0xffffffffu, v, o);
        if (tid == 0) g_delta = v / (float)NN;
    }
}

// ---------------------------------------------------------------------------
__global__ __launch_bounds__(THREADS, 1)
void pna_kernel(const __grid_constant__ CUtensorMap a_map,
                const __grid_constant__ CUtensorMap f_map,
                const float* __restrict__ Theta, const float* __restrict__ Bias,
                float* __restrict__ out) {
    extern __shared__ uint32_t smu[];
    const uint32_t sbase = smem_u32(smu);
    const uint32_t mb_full = sbase + MBAR_OFF;
    const uint32_t mb_done = sbase + MBAR_OFF + 32;

    const int tid = threadIdx.x, lane = tid & 31, wid = tid >> 5;
    const int lq = lane >> 2, lr = lane & 3;
    const int wm = wid >> 2, wn = wid & 3;
    const int bp = blockIdx.y, i0 = blockIdx.x * TM;
    const int b = bp / PP, p = bp % PP;

    if (tid == 0) {
        #pragma unroll
        for (int i = 0; i < NBUF; i++) {
            MBAR_INIT(mb_full + 8 * i, 1);
            MBAR_INIT(mb_done + 8 * i, 16);   // one arrive per warp
        }
    }
    __syncthreads();

    #define ISSUE(s) do {                                                     \
        int _bf = (s) & 1;                                                    \
        uint32_t _mb = mb_full + 8 * _bf;                                     \
        uint32_t _sb = sbase + _bf * SB_BYTES;                                \
        MBAR_EXPECT_TX(_mb, SB_BYTES);                                        \
        TMA_LOAD_2D(_sb,         &a_map, (s) * KT,      i0, _mb);             \
        TMA_LOAD_2D(_sb + 16384, &a_map, (s) * KT + 64, i0, _mb);             \
        TMA_LOAD_2D(_sb + 32768, &f_map, (s) * KT,      bp * 256, _mb);       \
        TMA_LOAD_2D(_sb + 65536, &f_map, (s) * KT + 64, bp * 256, _mb);       \
    } while (0)

    const int rowA = wm * 32 + (lane & 7) + ((lane >> 3) & 1) * 8;
    const uint32_t xorA = (uint32_t)((rowA & 7) << 4);
    const uint32_t colA = (uint32_t)(((lane >> 4) & 1) * 16);
    const uint32_t aoffb = (uint32_t)(rowA * 128);
    const int rowB = wn * 64 + (lane & 7) + ((lane >> 4) & 1) * 8;
    const uint32_t xorB = (uint32_t)((rowB & 7) << 4);
    const uint32_t colB = (uint32_t)(((lane >> 3) & 1) * 16);
    const uint32_t boffb = (uint32_t)(rowB * 128);

    float acc[2][8][4];
    #pragma unroll
    for (int mt = 0; mt < 2; mt++)
        #pragma unroll
        for (int nt = 0; nt < 8; nt++)
            #pragma unroll
            for (int j = 0; j < 4; j++) acc[mt][nt][j] = 0.f;

    if (tid == 0) { ISSUE(0); ISSUE(1); }

    const int NST = NN / KT;   // 16
    for (int s = 0; s < NST; s++) {
        // consumer: wait data for stage s (buffer s&1, phase (s>>1)&1)
        MBAR_WAIT(mb_full + 8 * (s & 1), (s >> 1) & 1);

        const uint32_t stg = sbase + (uint32_t)((s & 1) * SB_BYTES);
        #pragma unroll
        for (int kb = 0; kb < 8; kb++) {
            const uint32_t asub = stg + (uint32_t)(kb >> 2) * 16384;
            const uint32_t fsub = stg + 32768 + (uint32_t)(kb >> 2) * 32768;
            const uint32_t ac = ((uint32_t)((kb & 3) * 32) + colA) ^ xorA;
            const uint32_t bc = ((uint32_t)((kb & 3) * 32) + colB) ^ xorB;
            uint32_t af[2][4], bf[4][4];
            #pragma unroll
            for (int mt = 0; mt < 2; mt++)
                ldsm_x4(af[mt], asub + aoffb + mt * 2048 + ac);
            #pragma unroll
            for (int ntp = 0; ntp < 4; ntp++)
                ldsm_x4(bf[ntp], fsub + boffb + ntp * 2048 + bc);
            // early release: after this warp's LAST ldsm of the stage,
            // before the remaining MMAs — frags are in registers.
            if (kb == 7 && lane == 0) MBAR_ARRIVE(mb_done + 8 * (s & 1));
            #pragma unroll
            for (int mt = 0; mt < 2; mt++)
                #pragma unroll
                for (int nt = 0; nt < 8; nt++)
                    mma_f16(acc[mt][nt], af[mt], bf[nt >> 1][(nt & 1) * 2],
                            bf[nt >> 1][(nt & 1) * 2 + 1]);
        }
        // producer: refill buffer s&1 for stage s+2 once all 16 warps released it
        if (tid == 0 && s + 2 < NST) {
            MBAR_WAIT(mb_done + 8 * (s & 1), (s >> 1) & 1);
            ISSUE(s + 2);
        }
    }
    #undef ISSUE
    __syncthreads();   // all warps past mainloop before epilogue reuses the ring

    // ---- spill accumulators to ACC[128][264] f32 ----
    float* ACCf = reinterpret_cast<float*>(smu);
    #pragma unroll
    for (int mt = 0; mt < 2; mt++) {
        int r = wm * 32 + mt * 16 + lq;
        #pragma unroll
        for (int nt = 0; nt < 8; nt++) {
            int c = wn * 64 + nt * 8 + lr * 2;
            float* a = acc[mt][nt];
            ACCf[r * ACCS + c]           = a[0];
            ACCf[r * ACCS + c + 1]       = a[1];
            ACCf[(r + 8) * ACCS + c]     = a[2];
            ACCf[(r + 8) * ACCS + c + 1] = a[3];
        }
    }
    __syncthreads();

    // ---- phase A: aggregators -> feats fp16 ----
    __half* Fbh = reinterpret_cast<__half*>(smu + FEAT_OFF);
    const float* xp = g_xp + (size_t)bp * NN * CC;
    for (int e = tid; e < TM * 32; e += THREADS) {
        int il = e >> 5, ch = e & 31;
        const float* row = &ACCf[il * ACCS];
        float S1  = row[ch],       S2  = row[32 + ch];
        float S3  = row[64 + ch],  S4  = row[96 + ch];
        float SXP = row[128 + ch], SEP = row[160 + ch];
        float SXN = row[192 + ch], SEN = row[224 + ch];

        int i = i0 + il;
        float x    = xp[(size_t)i * CC + ch];
        float dg   = g_deg[i];
        float dinv = 1.f / fmaxf(dg, EPSV);
        float m1 = S1 * dinv, m2 = S2 * dinv, m3 = S3 * dinv, m4 = S4 * dinv;
        float smax = SXP / (SEP + EPSV);
        float smin = SXN / (SEN + EPSV);
        float var  = fmaxf(m2 - m1 * m1, 0.f);
        float stdv = sqrtf(var + EPSV);
        float x2 = x * x, x3 = x2 * x, x4 = x2 * x2;
        float dist = x2 - 2.f * x * m1 + m2;
        float ed2  = x4 - 4.f * x3 * m1 + 6.f * x2 * m2 - 4.f * x * m3 + m4;
        float dstd = sqrtf(fmaxf(ed2 - dist * dist, 0.f) + EPSV);

        __half* fr = Fbh + (size_t)il * (2 * FBS);
        fr[0 * 32 + ch] = __float2half(smin);
        fr[1 * 32 + ch] = __float2half(smax);
        fr[2 * 32 + ch] = __float2half(m1);
        fr[3 * 32 + ch] = __float2half(stdv);
        fr[4 * 32 + ch] = __float2half(var);
        fr[5 * 32 + ch] = __float2half(dist);
        fr[6 * 32 + ch] = __float2half(dstd);
    }
    __syncthreads();

    // ---- stage ThetaB fp16 into dead ACC region ----
    for (int idx = tid; idx < 96 * 112; idx += THREADS) {
        int p2 = idx / 96, n = idx % 96;
        int q = n >> 5, o = n & 31;
        float f0 = Theta[(size_t)(224 * q + 2 * p2) * OUTC + o];
        float f1 = Theta[(size_t)(224 * q + 2 * p2 + 1) * OUTC + o];
        smu[THB_OFF + n * FBS + p2] = pack_h2(f0, f1);
    }
    __syncthreads();

    // ---- GEMM2 (fp16): D[128][96] = feats[128x224] @ ThetaB^T ----
    {
        const uint32_t* Fb = smu + FEAT_OFF;
        const uint32_t* Tb = smu + THB_OFF;
        const int wm2 = wid >> 1, wn2 = wid & 1;
        float a2[6][4];
        #pragma unroll
        for (int nt = 0; nt < 6; nt++)
            #pragma unroll
            for (int j = 0; j < 4; j++) a2[nt][j] = 0.f;

        #pragma unroll 2
        for (int kb = 0; kb < 14; kb++) {
            uint32_t af[4], bfv[6][2];
            int r = (wm2 * 16 + lq) * FBS + kb * 8 + lr;
            af[0] = Fb[r];
            af[1] = Fb[r + 8 * FBS];
            af[2] = Fb[r + 4];
            af[3] = Fb[r + 8 * FBS + 4];
            #pragma unroll
            for (int nt = 0; nt < 6; nt++) {
                int c = (wn2 * 48 + nt * 8 + lq) * FBS + kb * 8 + lr;
                bfv[nt][0] = Tb[c];
                bfv[nt][1] = Tb[c + 4];
            }
            #pragma unroll
            for (int nt = 0; nt < 6; nt++)
                mma_f16(a2[nt], af, bfv[nt][0], bfv[nt][1]);
        }
        __syncthreads();
        float* D = reinterpret_cast<float*>(smu + D_OFF);
        int r = wm2 * 16 + lq;
        #pragma unroll
        for (int nt = 0; nt < 6; nt++) {
            int c = wn2 * 48 + nt * 8 + 2 * lr;
            D[r * 100 + c]           = a2[nt][0];
            D[r * 100 + c + 1]       = a2[nt][1];
            D[(r + 8) * 100 + c]     = a2[nt][2];
            D[(r + 8) * 100 + c + 1] = a2[nt][3];
        }
        __syncthreads();

        int i = tid >> 2;
        int ob = (tid & 3) * 8;
        float dg = g_deg[i0 + i];
        float sv = logf(dg + 1.f) / g_delta;
        float iv = 1.f / fmaxf(sv, EPSV);
        #pragma unroll
        for (int k = 0; k < 8; k++) {
            int o = ob + k;
            float v = D[i * 100 + o] + sv * D[i * 100 + 32 + o] +
                      iv * D[i * 100 + 64 + o] + Bias[o];
            v = v > 0.f ? v : NEG_SLOPE * v;
            out[(((size_t)b * OUTC + o) * NN + (i0 + i)) * PP + p] = v;
        }
    }
}

// ---------------------------------------------------------------------------
typedef CUresult (*PFN_encodeTiled)(CUtensorMap*, CUtensorMapDataType, cuuint32_t,
                                    void*, const cuuint64_t*, const cuuint64_t*,
                                    const cuuint32_t*, const cuuint32_t*,
                                    CUtensorMapInterleave, CUtensorMapSwizzle,
                                    CUtensorMapL2promotion, CUtensorMapFloatOOBfill);

extern "C" void kernel_launch(void* const* d_in, const int* in_sizes, int n_in,
                              void* d_out, int out_size) {
    const float* X     = (const float*)d_in[0];
    const float* A     = (const float*)d_in[1];
    const float* Theta = (const float*)d_in[2];
    const float* Bias  = (const float*)d_in[3];
    float* out = (float*)d_out;

    void* fn = nullptr;
    cudaDriverEntryPointQueryResult qr;
#if CUDART_VERSION >= 12050
    cudaGetDriverEntryPointByVersion("cuTensorMapEncodeTiled", &fn, 12000,
                                     cudaEnableDefault, &qr);
#else
    cudaGetDriverEntryPoint("cuTensorMapEncodeTiled", &fn, cudaEnableDefault, &qr);
#endif
    PFN_encodeTiled encode = (PFN_encodeTiled)fn;

    void *dA = nullptr, *dF = nullptr;
    cudaGetSymbolAddress(&dA, g_ahf);
    cudaGetSymbolAddress(&dF, g_fhf);

    CUtensorMap a_map, f_map;
    {
        cuuint64_t dims[2]    = {NN, NN};
        cuuint64_t strides[1] = {(cuuint64_t)NN * 2};
        cuuint32_t box[2]     = {64, 128};
        cuuint32_t es[2]      = {1, 1};
        encode(&a_map, CU_TENSOR_MAP_DATA_TYPE_FLOAT16, 2, dA, dims, strides, box, es,
               CU_TENSOR_MAP_INTERLEAVE_NONE, CU_TENSOR_MAP_SWIZZLE_128B,
               CU_TENSOR_MAP_L2_PROMOTION_L2_128B, CU_TENSOR_MAP_FLOAT_OOB_FILL_NONE);
    }
    {
        cuuint64_t dims[2]    = {NN, (cuuint64_t)BB * PP * 256};
        cuuint64_t strides[1] = {(cuuint64_t)NN * 2};
        cuuint32_t box[2]     = {64, 256};
        cuuint32_t es[2]      = {1, 1};
        encode(&f_map, CU_TENSOR_MAP_DATA_TYPE_FLOAT16, 2, dF, dims, strides, box, es,
               CU_TENSOR_MAP_INTERLEAVE_NONE, CU_TENSOR_MAP_SWIZZLE_128B,
               CU_TENSOR_MAP_L2_PROMOTION_L2_128B, CU_TENSOR_MAP_FLOAT_OOB_FILL_NONE);
    }

    cudaFuncSetAttribute(pna_kernel, cudaFuncAttributeMaxDynamicSharedMemorySize,
                         SMEM_BYTES);
    cudaFuncSetAttribute(prep_kernel, cudaFuncAttributeMaxDynamicSharedMemorySize,
                         CC * SXS * 4);

    prep_kernel<<<dim3(NN / 32, BB + 1), 256, CC * SXS * 4>>>(X, A);
    delta_kernel<<<1, 1024>>>();

    dim3 grid(NN / TM, BB * PP);
    pna_kernel<<<grid, THREADS, SMEM_BYTES>>>(a_map, f_map, Theta, Bias, out);
}

// round 17
// speedup vs baseline: 2.0487x; 1.0115x over previous
#include <cuda_runtime.h>
#include <cuda_fp16.h>
#include <cuda.h>
#include <math.h>
#include <stdint.h>

#define BB   4
#define CC   32
#define NN   2048
#define PP   12
#define OUTC 32
#define TM   128
#define KT   128
#define THREADS 512
#define EPSV 1e-5f
#define NEG_SLOPE 0.01f

// ---- pna smem layout ----
#define SB_BYTES  98304
#define NBUF      2
#define MBAR_OFF  196608        // full[2] @ +0, done[2] @ +32
#define SMEM_BYTES 196736
#define ACCS     264
#define FEAT_OFF 33792
#define FBS      116
#define THB_OFF  0
#define D_OFF    12800

__device__ __align__(1024) __half g_ahf[(size_t)NN * NN];
__device__ __align__(1024) __half g_fhf[(size_t)BB * PP * 256 * NN];
__device__ float g_xp[(size_t)BB * PP * NN * CC];
__device__ float g_deg[NN];
__device__ float g_delta;

// ---------------------------------------------------------------------------
__device__ __forceinline__ uint32_t smem_u32(const void* p) {
    uint32_t a;
    asm("{ .reg .u64 t; cvta.to.shared.u64 t, %1; cvt.u32.u64 %0, t; }" : "=r"(a) : "l"(p));
    return a;
}
#define MBAR_INIT(a, n) \
    asm volatile("mbarrier.init.shared.b64 [%0], %1;" :: "r"(a), "r"(n) : "memory")
#define MBAR_EXPECT_TX(a, bytes) \
    asm volatile("mbarrier.arrive.expect_tx.shared.b64 _, [%0], %1;" :: "r"(a), "r"(bytes) : "memory")
#define MBAR_ARRIVE(a) \
    asm volatile("mbarrier.arrive.shared.b64 _, [%0];" :: "r"(a) : "memory")
#define MBAR_WAIT(a, ph) do { \
    asm volatile("{\n\t.reg .pred P1;\n\tWL_%=:\n\t" \
        "mbarrier.try_wait.parity.acquire.cta.shared::cta.b64 P1, [%0], %1, 0x989680;\n\t" \
        "@P1 bra.uni WD_%=;\n\tbra.uni WL_%=;\n\tWD_%=:\n\t}" \
        :: "r"(a), "r"(ph) : "memory"); } while (0)
#define TMA_LOAD_2D(saddr, map, cx, cy, mbar) \
    asm volatile("cp.async.bulk.tensor.2d.shared::cta.global.tile.mbarrier::complete_tx::bytes " \
        "[%0], [%1, {%2, %3}], [%4];" \
        :: "r"((uint32_t)(saddr)), "l"(map), "r"((int)(cx)), "r"((int)(cy)), \
           "r"((uint32_t)(mbar)) : "memory")

__device__ __forceinline__ void ldsm_x4(uint32_t r[4], uint32_t addr) {
    asm volatile("ldmatrix.sync.aligned.m8n8.x4.shared.b16 {%0,%1,%2,%3}, [%4];"
        : "=r"(r[0]), "=r"(r[1]), "=r"(r[2]), "=r"(r[3]) : "r"(addr));
}
__device__ __forceinline__ void mma_f16(float c[4], const uint32_t a[4],
                                        const uint32_t b0, const uint32_t b1) {
    asm volatile(
        "mma.sync.aligned.m16n8k16.row.col.f32.f16.f16.f32 "
        "{%0,%1,%2,%3}, {%4,%5,%6,%7}, {%8,%9}, {%0,%1,%2,%3};"
        : "+f"(c[0]), "+f"(c[1]), "+f"(c[2]), "+f"(c[3])
        : "r"(a[0]), "r"(a[1]), "r"(a[2]), "r"(a[3]), "r"(b0), "r"(b1));
}
__device__ __forceinline__ uint32_t pack_h2(float lo, float hi) {
    __half2 h = __floats2half2_rn(lo, hi);
    return *reinterpret_cast<uint32_t*>(&h);
}

// ---------------------------------------------------------------------------
// fused prep: y<BB -> X transpose + feature planes ; y==BB -> A fp16 + degree
#define SXS 387
__global__ void prep_kernel(const float* __restrict__ X, const float* __restrict__ A) {
    const int t = threadIdx.x;   // 256
    const int lane = t & 31, w = t >> 5;

    if (blockIdx.y == BB) {
        #pragma unroll
        for (int it = 0; it < 4; it++) {
            int row = blockIdx.x * 32 + it * 8 + w;
            const float4* src = reinterpret_cast<const float4*>(A + (size_t)row * NN);
            uint32_t* dst = reinterpret_cast<uint32_t*>(g_ahf) + (size_t)row * (NN / 2);
            float s = 0.f;
            #pragma unroll
            for (int k = 0; k < 16; k++) {
                float4 v = src[lane + 32 * k];
                s += (v.x + v.y) + (v.z + v.w);
                dst[2 * (lane + 32 * k)]     = pack_h2(v.x, v.y);
                dst[2 * (lane + 32 * k) + 1] = pack_h2(v.z, v.w);
            }
            #pragma unroll
            for (int o = 16; o; o >>= 1) s += __shfl_xor_sync(0xffffffffu, s, o);
            if (lane == 0) g_deg[row] = s;
        }
        return;
    }

    extern __shared__ float sx[];
    const int b  = blockIdx.y;
    const int j0 = blockIdx.x * 32;

    #pragma unroll
    for (int i = 0; i < 48; i++) {
        int e = t + 256 * i;
        int ch = e / 384, rem = e - ch * 384;
        sx[ch * SXS + rem] = X[((size_t)(b * CC + ch) * NN + j0) * PP + rem];
    }
    __syncthreads();

    #pragma unroll
    for (int p = 0; p < PP; p++) {
        int bp = b * PP + p;
        float* xpd = g_xp + ((size_t)bp * NN + j0) * CC;
        #pragma unroll
        for (int i = 0; i < 4; i++) {
            int e = t + 256 * i;
            int j = e >> 5, ch = e & 31;
            xpd[j * CC + ch] = sx[ch * SXS + j * 12 + p];
        }
    }

    __half* fh = reinterpret_cast<__half*>(g_fhf);
    #pragma unroll
    for (int i = 0; i < 4; i++) {
        int ch = w + 8 * i;
        #pragma unroll
        for (int p = 0; p < PP; p++) {
            int bp = b * PP + p;
            float x = sx[ch * SXS + lane * 12 + p];
            float x2 = x * x;
            float ep = __expf(x), en = __expf(-x);
            size_t base = (((size_t)bp * 256 + ch) * NN + j0) + lane;
            const size_t G = (size_t)32 * NN;
            fh[base + 0 * G] = __float2half(x);
            fh[base + 1 * G] = __float2half(x2);
            fh[base + 2 * G] = __float2half(x2 * x);
            fh[base + 3 * G] = __float2half(x2 * x2);
            fh[base + 4 * G] = __float2half(x * ep);
            fh[base + 5 * G] = __float2half(ep);
            fh[base + 6 * G] = __float2half(x * en);
            fh[base + 7 * G] = __float2half(en);
        }
    }
}

__global__ void delta_kernel() {
    __shared__ float red[32];
    int tid = threadIdx.x;
    float s = 0.f;
    for (int i = tid; i < NN; i += blockDim.x) s += __logf(g_deg[i] + 1.f);
    #pragma unroll
    for (int o = 16; o; o >>= 1) s += __shfl_xor_sync(0xffffffffu, s, o);
    if ((tid & 31) == 0) red[tid >> 5] = s;
    __syncthreads();
    if (tid < 32) {
        float v = (tid < (int)(blockDim.x >> 5)) ? red[tid] : 0.f;
        #pragma unroll
        for (int o = 16; o; o >>= 1) v += __shfl_xor_sync(0xffffffffu, v, o);
        if (tid == 0) g_delta = v / (float)NN;
    }
}

// ---------------------------------------------------------------------------
__global__ __launch_bounds__(THREADS, 1)
void pna_kernel(const __grid_constant__ CUtensorMap a_map,
                const __grid_constant__ CUtensorMap f_map,
                const float* __restrict__ Theta, const float* __restrict__ Bias,
                float* __restrict__ out) {
    extern __shared__ uint32_t smu[];
    const uint32_t sbase = smem_u32(smu);
    const uint32_t mb_full = sbase + MBAR_OFF;
    const uint32_t mb_done = sbase + MBAR_OFF + 32;

    const int tid = threadIdx.x, lane = tid & 31, wid = tid >> 5;
    const int lq = lane >> 2, lr = lane & 3;
    const int wm = wid >> 2, wn = wid & 3;
    const int bp = blockIdx.y, i0 = blockIdx.x * TM;
    const int b = bp / PP, p = bp % PP;

    if (tid == 0) {
        #pragma unroll
        for (int i = 0; i < NBUF; i++) {
            MBAR_INIT(mb_full + 8 * i, 1);
            MBAR_INIT(mb_done + 8 * i, 16);
        }
    }
    __syncthreads();

    #define ISSUE(s) do {                                                     \
        int _bf = (s) & 1;                                                    \
        uint32_t _mb = mb_full + 8 * _bf;                                     \
        uint32_t _sb = sbase + _bf * SB_BYTES;                                \
        MBAR_EXPECT_TX(_mb, SB_BYTES);                                        \
        TMA_LOAD_2D(_sb,         &a_map, (s) * KT,      i0, _mb);             \
        TMA_LOAD_2D(_sb + 16384, &a_map, (s) * KT + 64, i0, _mb);             \
        TMA_LOAD_2D(_sb + 32768, &f_map, (s) * KT,      bp * 256, _mb);       \
        TMA_LOAD_2D(_sb + 65536, &f_map, (s) * KT + 64, bp * 256, _mb);       \
    } while (0)

    const int rowA = wm * 32 + (lane & 7) + ((lane >> 3) & 1) * 8;
    const uint32_t xorA = (uint32_t)((rowA & 7) << 4);
    const uint32_t colA = (uint32_t)(((lane >> 4) & 1) * 16);
    const uint32_t aoffb = (uint32_t)(rowA * 128);
    const int rowB = wn * 64 + (lane & 7) + ((lane >> 4) & 1) * 8;
    const uint32_t xorB = (uint32_t)((rowB & 7) << 4);
    const uint32_t colB = (uint32_t)(((lane >> 3) & 1) * 16);
    const uint32_t boffb = (uint32_t)(rowB * 128);

    float acc[2][8][4];
    #pragma unroll
    for (int mt = 0; mt < 2; mt++)
        #pragma unroll
        for (int nt = 0; nt < 8; nt++)
            #pragma unroll
            for (int j = 0; j < 4; j++) acc[mt][nt][j] = 0.f;

    if (tid == 0) { ISSUE(0); ISSUE(1); }

    const int NST = NN / KT;   // 16
    for (int s = 0; s < NST; s++) {
        MBAR_WAIT(mb_full + 8 * (s & 1), (s >> 1) & 1);

        const uint32_t stg = sbase + (uint32_t)((s & 1) * SB_BYTES);
        #pragma unroll
        for (int kb = 0; kb < 8; kb++) {
            const uint32_t asub = stg + (uint32_t)(kb >> 2) * 16384;
            const uint32_t fsub = stg + 32768 + (uint32_t)(kb >> 2) * 32768;
            const uint32_t ac = ((uint32_t)((kb & 3) * 32) + colA) ^ xorA;
            const uint32_t bc = ((uint32_t)((kb & 3) * 32) + colB) ^ xorB;
            uint32_t af[2][4], bf[4][4];
            #pragma unroll
            for (int mt = 0; mt < 2; mt++)
                ldsm_x4(af[mt], asub + aoffb + mt * 2048 + ac);
            #pragma unroll
            for (int ntp = 0; ntp < 4; ntp++)
                ldsm_x4(bf[ntp], fsub + boffb + ntp * 2048 + bc);
            if (kb == 7 && lane == 0) MBAR_ARRIVE(mb_done + 8 * (s & 1));
            #pragma unroll
            for (int mt = 0; mt < 2; mt++)
                #pragma unroll
                for (int nt = 0; nt < 8; nt++)
                    mma_f16(acc[mt][nt], af[mt], bf[nt >> 1][(nt & 1) * 2],
                            bf[nt >> 1][(nt & 1) * 2 + 1]);
        }
        if (tid == 0 && s + 2 < NST) {
            MBAR_WAIT(mb_done + 8 * (s & 1), (s >> 1) & 1);
            ISSUE(s + 2);
        }
    }
    #undef ISSUE
    __syncthreads();

    // ---- spill accumulators to ACC[128][264] f32 ----
    float* ACCf = reinterpret_cast<float*>(smu);
    #pragma unroll
    for (int mt = 0; mt < 2; mt++) {
        int r = wm * 32 + mt * 16 + lq;
        #pragma unroll
        for (int nt = 0; nt < 8; nt++) {
            int c = wn * 64 + nt * 8 + lr * 2;
            float* a = acc[mt][nt];
            ACCf[r * ACCS + c]           = a[0];
            ACCf[r * ACCS + c + 1]       = a[1];
            ACCf[(r + 8) * ACCS + c]     = a[2];
            ACCf[(r + 8) * ACCS + c + 1] = a[3];
        }
    }
    __syncthreads();

    // ---- phase A: aggregators -> feats fp16 ----
    __half* Fbh = reinterpret_cast<__half*>(smu + FEAT_OFF);
    const float* xp = g_xp + (size_t)bp * NN * CC;
    for (int e = tid; e < TM * 32; e += THREADS) {
        int il = e >> 5, ch = e & 31;
        const float* row = &ACCf[il * ACCS];
        float S1  = row[ch],       S2  = row[32 + ch];
        float S3  = row[64 + ch],  S4  = row[96 + ch];
        float SXP = row[128 + ch], SEP = row[160 + ch];
        float SXN = row[192 + ch], SEN = row[224 + ch];

        int i = i0 + il;
        float x    = xp[(size_t)i * CC + ch];
        float dg   = g_deg[i];
        float dinv = __fdividef(1.f, fmaxf(dg, EPSV));
        float m1 = S1 * dinv, m2 = S2 * dinv, m3 = S3 * dinv, m4 = S4 * dinv;
        float smax = __fdividef(SXP, SEP + EPSV);
        float smin = __fdividef(SXN, SEN + EPSV);
        float var  = fmaxf(m2 - m1 * m1, 0.f);
        float stdv = __fsqrt_rn(var + EPSV);
        float x2 = x * x, x3 = x2 * x, x4 = x2 * x2;
        float dist = x2 - 2.f * x * m1 + m2;
        float ed2  = x4 - 4.f * x3 * m1 + 6.f * x2 * m2 - 4.f * x * m3 + m4;
        float dstd = __fsqrt_rn(fmaxf(ed2 - dist * dist, 0.f) + EPSV);

        __half* fr = Fbh + (size_t)il * (2 * FBS);
        fr[0 * 32 + ch] = __float2half(smin);
        fr[1 * 32 + ch] = __float2half(smax);
        fr[2 * 32 + ch] = __float2half(m1);
        fr[3 * 32 + ch] = __float2half(stdv);
        fr[4 * 32 + ch] = __float2half(var);
        fr[5 * 32 + ch] = __float2half(dist);
        fr[6 * 32 + ch] = __float2half(dstd);
    }
    __syncthreads();

    // ---- stage ThetaB fp16 into dead ACC region ----
    for (int idx = tid; idx < 96 * 112; idx += THREADS) {
        int p2 = idx / 96, n = idx - p2 * 96;
        int q = n >> 5, o = n & 31;
        float f0 = Theta[(size_t)(224 * q + 2 * p2) * OUTC + o];
        float f1 = Theta[(size_t)(224 * q + 2 * p2 + 1) * OUTC + o];
        smu[THB_OFF + n * FBS + p2] = pack_h2(f0, f1);
    }
    __syncthreads();

    // ---- GEMM2 (fp16): D[128][96] = feats[128x224] @ ThetaB^T ----
    {
        const uint32_t* Fb = smu + FEAT_OFF;
        const uint32_t* Tb = smu + THB_OFF;
        const int wm2 = wid >> 1, wn2 = wid & 1;
        float a2[6][4];
        #pragma unroll
        for (int nt = 0; nt < 6; nt++)
            #pragma unroll
            for (int j = 0; j < 4; j++) a2[nt][j] = 0.f;

        #pragma unroll 2
        for (int kb = 0; kb < 14; kb++) {
            uint32_t af[4], bfv[6][2];
            int r = (wm2 * 16 + lq) * FBS + kb * 8 + lr;
            af[0] = Fb[r];
            af[1] = Fb[r + 8 * FBS];
            af[2] = Fb[r + 4];
            af[3] = Fb[r + 8 * FBS + 4];
            #pragma unroll
            for (int nt = 0; nt < 6; nt++) {
                int c = (wn2 * 48 + nt * 8 + lq) * FBS + kb * 8 + lr;
                bfv[nt][0] = Tb[c];
                bfv[nt][1] = Tb[c + 4];
            }
            #pragma unroll
            for (int nt = 0; nt < 6; nt++)
                mma_f16(a2[nt], af, bfv[nt][0], bfv[nt][1]);
        }
        __syncthreads();
        float* D = reinterpret_cast<float*>(smu + D_OFF);
        int r = wm2 * 16 + lq;
        #pragma unroll
        for (int nt = 0; nt < 6; nt++) {
            int c = wn2 * 48 + nt * 8 + 2 * lr;
            D[r * 100 + c]           = a2[nt][0];
            D[r * 100 + c + 1]       = a2[nt][1];
            D[(r + 8) * 100 + c]     = a2[nt][2];
            D[(r + 8) * 100 + c + 1] = a2[nt][3];
        }
        __syncthreads();

        int i = tid >> 2;
        int ob = (tid & 3) * 8;
        float dg = g_deg[i0 + i];
        float sv = __fdividef(__logf(dg + 1.f), g_delta);
        float iv = __fdividef(1.f, fmaxf(sv, EPSV));
        #pragma unroll
        for (int k = 0; k < 8; k++) {
            int o = ob + k;
            float v = D[i * 100 + o] + sv * D[i * 100 + 32 + o] +
                      iv * D[i * 100 + 64 + o] + Bias[o];
            v = v > 0.f ? v : NEG_SLOPE * v;
            out[(((size_t)b * OUTC + o) * NN + (i0 + i)) * PP + p] = v;
        }
    }
}

// ---------------------------------------------------------------------------
typedef CUresult (*PFN_encodeTiled)(CUtensorMap*, CUtensorMapDataType, cuuint32_t,
                                    void*, const cuuint64_t*, const cuuint64_t*,
                                    const cuuint32_t*, const cuuint32_t*,
                                    CUtensorMapInterleave, CUtensorMapSwizzle,
                                    CUtensorMapL2promotion, CUtensorMapFloatOOBfill);

extern "C" void kernel_launch(void* const* d_in, const int* in_sizes, int n_in,
                              void* d_out, int out_size) {
    const float* X     = (const float*)d_in[0];
    const float* A     = (const float*)d_in[1];
    const float* Theta = (const float*)d_in[2];
    const float* Bias  = (const float*)d_in[3];
    float* out = (float*)d_out;

    void* fn = nullptr;
    cudaDriverEntryPointQueryResult qr;
#if CUDART_VERSION >= 12050
    cudaGetDriverEntryPointByVersion("cuTensorMapEncodeTiled", &fn, 12000,
                                     cudaEnableDefault, &qr);
#else
    cudaGetDriverEntryPoint("cuTensorMapEncodeTiled", &fn, cudaEnableDefault, &qr);
#endif
    PFN_encodeTiled encode = (PFN_encodeTiled)fn;

    void *dA = nullptr, *dF = nullptr;
    cudaGetSymbolAddress(&dA, g_ahf);
    cudaGetSymbolAddress(&dF, g_fhf);

    CUtensorMap a_map, f_map;
    {
        cuuint64_t dims[2]    = {NN, NN};
        cuuint64_t strides[1] = {(cuuint64_t)NN * 2};
        cuuint32_t box[2]     = {64, 128};
        cuuint32_t es[2]      = {1, 1};
        encode(&a_map, CU_TENSOR_MAP_DATA_TYPE_FLOAT16, 2, dA, dims, strides, box, es,
               CU_TENSOR_MAP_INTERLEAVE_NONE, CU_TENSOR_MAP_SWIZZLE_128B,
               CU_TENSOR_MAP_L2_PROMOTION_L2_128B, CU_TENSOR_MAP_FLOAT_OOB_FILL_NONE);
    }
    {
        cuuint64_t dims[2]    = {NN, (cuuint64_t)BB * PP * 256};
        cuuint64_t strides[1] = {(cuuint64_t)NN * 2};
        cuuint32_t box[2]     = {64, 256};
        cuuint32_t es[2]      = {1, 1};
        encode(&f_map, CU_TENSOR_MAP_DATA_TYPE_FLOAT16, 2, dF, dims, strides, box, es,
               CU_TENSOR_MAP_INTERLEAVE_NONE, CU_TENSOR_MAP_SWIZZLE_128B,
               CU_TENSOR_MAP_L2_PROMOTION_L2_128B, CU_TENSOR_MAP_FLOAT_OOB_FILL_NONE);
    }

    cudaFuncSetAttribute(pna_kernel, cudaFuncAttributeMaxDynamicSharedMemorySize,
                         SMEM_BYTES);
    cudaFuncSetAttribute(prep_kernel, cudaFuncAttributeMaxDynamicSharedMemorySize,
                         CC * SXS * 4);

    prep_kernel<<<dim3(NN / 32, BB + 1), 256, CC * SXS * 4>>>(X, A);
    delta_kernel<<<1, 1024>>>();

    dim3 grid(NN / TM, BB * PP);
    pna_kernel<<<grid, THREADS, SMEM_BYTES>>>(a_map, f_map, Theta, Bias, out);
}